// round 12
// baseline (speedup 1.0000x reference)
#include <cuda_runtime.h>
#include <cuda_fp16.h>
#include <math.h>
#include <stdint.h>

#define S_LEN 2048
#define DIMN  2048
#define NH    16
#define NKV   4
#define HD    128
#define ROWS  4096   // B*S

// ---------------- scratch (device globals; no allocation allowed) ----------
__device__ __half g_xn_h[ROWS * DIMN];
__device__ __half g_xn_l[ROWS * DIMN];
__device__ __half g_wq_h[DIMN * DIMN];
__device__ __half g_wq_l[DIMN * DIMN];
__device__ __half g_wk_h[512 * DIMN];
__device__ __half g_wk_l[512 * DIMN];
__device__ __half g_wv_h[512 * DIMN];    // single fp16 (2-term V proj)
__device__ __half g_wo_h[DIMN * DIMN];   // single fp16 (2-term o_gemm)
__device__ __half g_qh[ROWS * DIMN];  // roped+scaled Q hi/lo
__device__ __half g_ql[ROWS * DIMN];
__device__ __half g_kh[ROWS * 512];   // roped K hi/lo
__device__ __half g_kl[ROWS * 512];
__device__ __half g_v [ROWS * 512];   // V single fp16
__device__ __half g_ao[ROWS * DIMN];  // attention output, fp16
__device__ int   g_cs[2 * S_LEN];     // per-batch inclusive cumsum of labels

// ---------------- helpers ----------------------------------------------------
__device__ __forceinline__ uint32_t smem_to_u32(const void* p) {
    uint32_t a;
    asm("{ .reg .u64 t; cvta.to.shared.u64 t, %1; cvt.u32.u64 %0, t; }" : "=r"(a) : "l"(p));
    return a;
}
__device__ __forceinline__ void ldmx4(uint32_t* r, uint32_t addr) {
    asm volatile("ldmatrix.sync.aligned.m8n8.x4.shared.b16 {%0,%1,%2,%3}, [%4];"
        : "=r"(r[0]), "=r"(r[1]), "=r"(r[2]), "=r"(r[3]) : "r"(addr));
}
__device__ __forceinline__ void ldmx4t(uint32_t* r, uint32_t addr) {
    asm volatile("ldmatrix.sync.aligned.m8n8.x4.trans.shared.b16 {%0,%1,%2,%3}, [%4];"
        : "=r"(r[0]), "=r"(r[1]), "=r"(r[2]), "=r"(r[3]) : "r"(addr));
}
__device__ __forceinline__ void mma16816(float* c, const uint32_t* a, const uint32_t* b) {
    asm volatile(
        "mma.sync.aligned.m16n8k16.row.col.f32.f16.f16.f32 "
        "{%0,%1,%2,%3}, {%4,%5,%6,%7}, {%8,%9}, {%0,%1,%2,%3};"
        : "+f"(c[0]), "+f"(c[1]), "+f"(c[2]), "+f"(c[3])
        : "r"(a[0]), "r"(a[1]), "r"(a[2]), "r"(a[3]), "r"(b[0]), "r"(b[1]));
}
__device__ __forceinline__ void cp16(uint32_t d, const void* s) {
    asm volatile("cp.async.ca.shared.global [%0], [%1], 16;" :: "r"(d), "l"(s));
}
__device__ __forceinline__ void pack_hilo(float x, float y, uint32_t& h, uint32_t& l) {
    __half2 hb = __floats2half2_rn(x, y);
    float rx = x - __low2float(hb);
    float ry = y - __high2float(hb);
    __half2 lb = __floats2half2_rn(rx, ry);
    h = *(uint32_t*)&hb;
    l = *(uint32_t*)&lb;
}
__device__ __forceinline__ uint32_t pack_h(float x, float y) {
    __half2 hb = __floats2half2_rn(x, y);
    return *(uint32_t*)&hb;
}

// ---------------- cumsum of seizure labels (per batch) ---------------------
__global__ void cumsum_kernel(const int* __restrict__ labels) {
    __shared__ int bufA[S_LEN], bufB[S_LEN];
    int b = blockIdx.x;
    for (int i = threadIdx.x; i < S_LEN; i += blockDim.x)
        bufA[i] = labels[b * S_LEN + i];
    __syncthreads();
    int* src = bufA; int* dst = bufB;
    for (int off = 1; off < S_LEN; off <<= 1) {
        for (int i = threadIdx.x; i < S_LEN; i += blockDim.x)
            dst[i] = src[i] + (i >= off ? src[i - off] : 0);
        __syncthreads();
        int* t = src; src = dst; dst = t;
    }
    for (int i = threadIdx.x; i < S_LEN; i += blockDim.x)
        g_cs[b * S_LEN + i] = src[i];
}

// ---------------- merged weight split (all 4 weights in one launch) ---------
#define WQ_F4 1048576   // 2048*2048/4
#define WK_F4 262144    // 512*2048/4
#define WV_F4 262144
#define WO_F4 1048576
#define TOT_F4 (WQ_F4 + WK_F4 + WV_F4 + WO_F4)

__global__ void split_all(const float* __restrict__ wq, const float* __restrict__ wk,
                          const float* __restrict__ wv, const float* __restrict__ wo) {
    int i = blockIdx.x * blockDim.x + threadIdx.x;
    if (i >= TOT_F4) return;
    const float* src; __half *hi, *lo; int j = i;
    if (j < WQ_F4) { src = wq; hi = g_wq_h; lo = g_wq_l; }
    else if ((j -= WQ_F4) < WK_F4) { src = wk; hi = g_wk_h; lo = g_wk_l; }
    else if ((j -= WK_F4) < WV_F4) { src = wv; hi = g_wv_h; lo = nullptr; }
    else { j -= WV_F4; src = wo; hi = g_wo_h; lo = nullptr; }
    float4 v = ((const float4*)src)[j];
    uint32_t h01, h23, l01, l23;
    pack_hilo(v.x, v.y, h01, l01);
    pack_hilo(v.z, v.w, h23, l23);
    *(uint2*)(hi + (size_t)j * 4) = make_uint2(h01, h23);
    if (lo) *(uint2*)(lo + (size_t)j * 4) = make_uint2(l01, l23);
}

// ---------------- layernorm (fp32 in) -> fp16 hi/lo --------------------------
__global__ void ln_kernel(const float* __restrict__ in, const float* __restrict__ w,
                          const float* __restrict__ bvec,
                          __half* __restrict__ oh, __half* __restrict__ ol) {
    int row = blockIdx.x;
    const float* x = in + (size_t)row * DIMN;
    int tid = threadIdx.x;

    float4 v0 = *(const float4*)(x + tid * 4);
    float4 v1 = *(const float4*)(x + 1024 + tid * 4);
    float s  = v0.x + v0.y + v0.z + v0.w + v1.x + v1.y + v1.z + v1.w;
    float ss = v0.x*v0.x + v0.y*v0.y + v0.z*v0.z + v0.w*v0.w
             + v1.x*v1.x + v1.y*v1.y + v1.z*v1.z + v1.w*v1.w;
    #pragma unroll
    for (int off = 16; off; off >>= 1) {
        s  += __shfl_xor_sync(0xffffffffu, s,  off);
        ss += __shfl_xor_sync(0xffffffffu, ss, off);
    }
    __shared__ float rs[8], rss[8];
    __shared__ float s_mu, s_rstd;
    int wid = tid >> 5, lane = tid & 31;
    if (!lane) { rs[wid] = s; rss[wid] = ss; }
    __syncthreads();
    if (tid == 0) {
        float S = 0.f, SS = 0.f;
        #pragma unroll
        for (int i = 0; i < 8; ++i) { S += rs[i]; SS += rss[i]; }
        float mu = S / DIMN;
        s_mu = mu;
        s_rstd = rsqrtf(SS / DIMN - mu * mu + 1e-5f);
    }
    __syncthreads();
    float mu = s_mu, rstd = s_rstd;

    size_t base = (size_t)row * DIMN;
    #pragma unroll
    for (int half = 0; half < 2; ++half) {
        int off = half * 1024 + tid * 4;
        float4 v = half ? v1 : v0;
        float4 w4 = *(const float4*)(w + off);
        float4 b4 = *(const float4*)(bvec + off);
        float4 r;
        r.x = (v.x - mu) * rstd * w4.x + b4.x;
        r.y = (v.y - mu) * rstd * w4.y + b4.y;
        r.z = (v.z - mu) * rstd * w4.z + b4.z;
        r.w = (v.w - mu) * rstd * w4.w + b4.w;
        uint32_t h01, h23, l01, l23;
        pack_hilo(r.x, r.y, h01, l01);
        pack_hilo(r.z, r.w, h23, l23);
        *(uint2*)(oh + base + off) = make_uint2(h01, h23);
        *(uint2*)(ol + base + off) = make_uint2(l01, l23);
    }
}

// ---------------- layernorm (fp16 in) -> fp16 hi/lo --------------------------
__global__ void ln_kernel_h(const __half* __restrict__ in, const float* __restrict__ w,
                            const float* __restrict__ bvec,
                            __half* __restrict__ oh, __half* __restrict__ ol) {
    int row = blockIdx.x;
    const __half* x = in + (size_t)row * DIMN;
    int tid = threadIdx.x;

    // each thread: 8 halfs (256*8 = 2048)
    uint4 u = *(const uint4*)(x + tid * 8);
    __half2 hv[4] = {*(__half2*)&u.x, *(__half2*)&u.y, *(__half2*)&u.z, *(__half2*)&u.w};
    float e[8];
    #pragma unroll
    for (int i = 0; i < 4; ++i) {
        float2 f = __half22float2(hv[i]);
        e[2 * i] = f.x; e[2 * i + 1] = f.y;
    }
    float s = 0.f, ss = 0.f;
    #pragma unroll
    for (int i = 0; i < 8; ++i) { s += e[i]; ss += e[i] * e[i]; }
    #pragma unroll
    for (int off = 16; off; off >>= 1) {
        s  += __shfl_xor_sync(0xffffffffu, s,  off);
        ss += __shfl_xor_sync(0xffffffffu, ss, off);
    }
    __shared__ float rs[8], rss[8];
    __shared__ float s_mu, s_rstd;
    int wid = tid >> 5, lane = tid & 31;
    if (!lane) { rs[wid] = s; rss[wid] = ss; }
    __syncthreads();
    if (tid == 0) {
        float S = 0.f, SS = 0.f;
        #pragma unroll
        for (int i = 0; i < 8; ++i) { S += rs[i]; SS += rss[i]; }
        float mu = S / DIMN;
        s_mu = mu;
        s_rstd = rsqrtf(SS / DIMN - mu * mu + 1e-5f);
    }
    __syncthreads();
    float mu = s_mu, rstd = s_rstd;

    size_t base = (size_t)row * DIMN + tid * 8;
    uint32_t hw[4], lw[4];
    #pragma unroll
    for (int i = 0; i < 4; ++i) {
        int off = tid * 8 + 2 * i;
        float2 w2 = *(const float2*)(w + off);
        float2 b2 = *(const float2*)(bvec + off);
        float rx = (e[2 * i]     - mu) * rstd * w2.x + b2.x;
        float ry = (e[2 * i + 1] - mu) * rstd * w2.y + b2.y;
        pack_hilo(rx, ry, hw[i], lw[i]);
    }
    *(uint4*)(oh + base) = make_uint4(hw[0], hw[1], hw[2], hw[3]);
    *(uint4*)(ol + base) = make_uint4(lw[0], lw[1], lw[2], lw[3]);
}

// ---------------- shared GEMM mainloops --------------------------------------
#define PITCH 80
#define TILE_B (128 * PITCH)
#define STAGE_B (4 * TILE_B)     // 2-stage 3-term
#define STAGE2_B (3 * TILE_B)    // 3-stage 2-term

__device__ __forceinline__ void cp_tile(uint32_t sdst, const __half* __restrict__ g,
                                        int row0, int K, int k0) {
    int tid = threadIdx.x;
    const char* gb = (const char*)(g + (size_t)row0 * K + k0);
    size_t rb = (size_t)K * 2;
    #pragma unroll
    for (int j = 0; j < 2; ++j) {
        int lin = j * 256 + tid;
        int r = lin >> 2, c = lin & 3;
        cp16(sdst + r * PITCH + c * 16, gb + (size_t)r * rb + c * 16);
    }
}

// 3-term mainloop (2 stages): D += Ah Bh + Ah Bl + Al Bh
__device__ __forceinline__ void gemm_mainloop(
        const __half* __restrict__ Ah, const __half* __restrict__ Al,
        const __half* __restrict__ Bh, const __half* __restrict__ Bl,
        int row0, int col0, int K, uint32_t sb, float acc[4][4][4]) {
    int tid = threadIdx.x, lane = tid & 31, wid = tid >> 5;
    int wm = wid & 1, wn = wid >> 1;

    const int nst = K >> 5;
    cp_tile(sb,              Ah, row0, K, 0);
    cp_tile(sb + TILE_B,     Al, row0, K, 0);
    cp_tile(sb + 2 * TILE_B, Bh, col0, K, 0);
    cp_tile(sb + 3 * TILE_B, Bl, col0, K, 0);
    asm volatile("cp.async.commit_group;" ::: "memory");

    for (int i = 0; i < nst; ++i) {
        asm volatile("cp.async.wait_group 0;" ::: "memory");
        __syncthreads();

        if (i + 1 < nst) {
            uint32_t pst = sb + ((i + 1) & 1) * STAGE_B;
            int k0 = (i + 1) << 5;
            cp_tile(pst,              Ah, row0, K, k0);
            cp_tile(pst + TILE_B,     Al, row0, K, k0);
            cp_tile(pst + 2 * TILE_B, Bh, col0, K, k0);
            cp_tile(pst + 3 * TILE_B, Bl, col0, K, k0);
            asm volatile("cp.async.commit_group;" ::: "memory");
        }

        uint32_t st = sb + (i & 1) * STAGE_B;
        uint32_t bh[4][4], bl[4][4];
        uint32_t bbase = st + 2 * TILE_B + (wn * 32 + (lane & 7)) * PITCH
                       + ((lane >> 3) & 1) * 16 + (lane >> 4) * 32;
        #pragma unroll
        for (int ni = 0; ni < 4; ++ni) ldmx4(bh[ni], bbase + ni * 8 * PITCH);
        #pragma unroll
        for (int ni = 0; ni < 4; ++ni) ldmx4(bl[ni], bbase + TILE_B + ni * 8 * PITCH);

        uint32_t abase = st + (wm * 64 + (lane & 15)) * PITCH + (lane >> 4) * 16;
        #pragma unroll
        for (int mi = 0; mi < 4; ++mi) {
            uint32_t ah0[4], al0[4], ah1[4], al1[4];
            uint32_t am = abase + mi * 16 * PITCH;
            ldmx4(ah0, am);
            ldmx4(al0, am + TILE_B);
            ldmx4(ah1, am + 32);
            ldmx4(al1, am + TILE_B + 32);
            #pragma unroll
            for (int ni = 0; ni < 4; ++ni) {
                mma16816(acc[mi][ni], ah0, bh[ni]);
                mma16816(acc[mi][ni], ah0, bl[ni]);
                mma16816(acc[mi][ni], al0, bh[ni]);
            }
            #pragma unroll
            for (int ni = 0; ni < 4; ++ni) {
                mma16816(acc[mi][ni], ah1, bh[ni] + 2);
                mma16816(acc[mi][ni], ah1, bl[ni] + 2);
                mma16816(acc[mi][ni], al1, bh[ni] + 2);
            }
        }
    }
    __syncthreads();
}

// 2-term mainloop (3 stages): D += Ah Bh + Al Bh
__device__ __forceinline__ void gemm_mainloop2(
        const __half* __restrict__ Ah, const __half* __restrict__ Al,
        const __half* __restrict__ Bh,
        int row0, int col0, int K, uint32_t sb, float acc[4][4][4]) {
    int tid = threadIdx.x, lane = tid & 31, wid = tid >> 5;
    int wm = wid & 1, wn = wid >> 1;

    const int nst = K >> 5;
    cp_tile(sb,              Ah, row0, K, 0);
    cp_tile(sb + TILE_B,     Al, row0, K, 0);
    cp_tile(sb + 2 * TILE_B, Bh, col0, K, 0);
    asm volatile("cp.async.commit_group;" ::: "memory");
    {
        uint32_t pst = sb + STAGE2_B;
        cp_tile(pst,              Ah, row0, K, 32);
        cp_tile(pst + TILE_B,     Al, row0, K, 32);
        cp_tile(pst + 2 * TILE_B, Bh, col0, K, 32);
        asm volatile("cp.async.commit_group;" ::: "memory");
    }

    int cbuf = 0, pbuf = 2;
    for (int i = 0; i < nst; ++i) {
        if (i + 1 < nst) asm volatile("cp.async.wait_group 1;" ::: "memory");
        else             asm volatile("cp.async.wait_group 0;" ::: "memory");
        __syncthreads();

        if (i + 2 < nst) {
            uint32_t pst = sb + pbuf * STAGE2_B;
            int k0 = (i + 2) << 5;
            cp_tile(pst,              Ah, row0, K, k0);
            cp_tile(pst + TILE_B,     Al, row0, K, k0);
            cp_tile(pst + 2 * TILE_B, Bh, col0, K, k0);
            asm volatile("cp.async.commit_group;" ::: "memory");
        }

        uint32_t st = sb + cbuf * STAGE2_B;
        uint32_t bh[4][4];
        uint32_t bbase = st + 2 * TILE_B + (wn * 32 + (lane & 7)) * PITCH
                       + ((lane >> 3) & 1) * 16 + (lane >> 4) * 32;
        #pragma unroll
        for (int ni = 0; ni < 4; ++ni) ldmx4(bh[ni], bbase + ni * 8 * PITCH);

        uint32_t abase = st + (wm * 64 + (lane & 15)) * PITCH + (lane >> 4) * 16;
        #pragma unroll
        for (int mi = 0; mi < 4; ++mi) {
            uint32_t ah0[4], al0[4], ah1[4], al1[4];
            uint32_t am = abase + mi * 16 * PITCH;
            ldmx4(ah0, am);
            ldmx4(al0, am + TILE_B);
            ldmx4(ah1, am + 32);
            ldmx4(al1, am + TILE_B + 32);
            #pragma unroll
            for (int ni = 0; ni < 4; ++ni) {
                mma16816(acc[mi][ni], ah0, bh[ni]);
                mma16816(acc[mi][ni], al0, bh[ni]);
            }
            #pragma unroll
            for (int ni = 0; ni < 4; ++ni) {
                mma16816(acc[mi][ni], ah1, bh[ni] + 2);
                mma16816(acc[mi][ni], al1, bh[ni] + 2);
            }
        }
        cbuf = (cbuf == 2) ? 0 : cbuf + 1;
        pbuf = (pbuf == 2) ? 0 : pbuf + 1;
    }
    __syncthreads();
}

// ---------------- merged QKV projection (one launch) ------------------------
// blockIdx.x: [0,16) -> Q (rope+scale, 3-term), [16,20) -> K (rope, 3-term),
//             [20,24) -> V (2-term, single fp16 out)
__global__ __launch_bounds__(256, 2)
void qkv_gemm(const float* __restrict__ fr, float qscale) {
    extern __shared__ char sm[];
    uint32_t sb = smem_to_u32(sm);
    int bx = blockIdx.x;
    int tid = threadIdx.x, lane = tid & 31, wid = tid >> 5;
    int wm = wid & 1, wn = wid >> 1;
    int row0 = blockIdx.y * 128;

    float acc[4][4][4];
    #pragma unroll
    for (int i = 0; i < 4; ++i)
        #pragma unroll
        for (int j = 0; j < 4; ++j)
            #pragma unroll
            for (int q = 0; q < 4; ++q) acc[i][j][q] = 0.f;

    __half *Oh, *Ol;
    int N, col0, do_rope;
    float scale;
    if (bx < 16) {
        Oh = g_qh; Ol = g_ql;
        N = DIMN; col0 = bx * 128; do_rope = 1; scale = qscale;
        gemm_mainloop(g_xn_h, g_xn_l, g_wq_h, g_wq_l, row0, col0, DIMN, sb, acc);
    } else if (bx < 20) {
        Oh = g_kh; Ol = g_kl;
        N = 512; col0 = (bx - 16) * 128; do_rope = 1; scale = 1.0f;
        gemm_mainloop(g_xn_h, g_xn_l, g_wk_h, g_wk_l, row0, col0, DIMN, sb, acc);
    } else {
        Oh = g_v; Ol = nullptr;
        N = 512; col0 = (bx - 20) * 128; do_rope = 0; scale = 1.0f;
        gemm_mainloop2(g_xn_h, g_xn_l, g_wv_h, row0, col0, DIMN, sb, acc);
    }

    int mrow = row0 + wm * 64 + (lane >> 2);
    int ncol = col0 + wn * 32 + (lane & 3) * 2;
    #pragma unroll
    for (int mi = 0; mi < 4; ++mi)
        #pragma unroll
        for (int ni = 0; ni < 4; ++ni) {
            int col = ncol + ni * 8;
            int r0 = mrow + mi * 16, r1 = r0 + 8;
            float x0 = acc[mi][ni][0], y0 = acc[mi][ni][1];
            float x1 = acc[mi][ni][2], y1 = acc[mi][ni][3];
            if (do_rope) {
                int fi = (col & 127) >> 1;
                int s0 = r0 & (S_LEN - 1), s1 = r1 & (S_LEN - 1);
                float c0 = fr[(s0 * 64 + fi) * 2], n0 = fr[(s0 * 64 + fi) * 2 + 1];
                float c1 = fr[(s1 * 64 + fi) * 2], n1 = fr[(s1 * 64 + fi) * 2 + 1];
                float tx0 = (x0 * c0 - y0 * n0) * scale;
                float ty0 = (x0 * n0 + y0 * c0) * scale;
                float tx1 = (x1 * c1 - y1 * n1) * scale;
                float ty1 = (x1 * n1 + y1 * c1) * scale;
                x0 = tx0; y0 = ty0; x1 = tx1; y1 = ty1;
            }
            uint32_t h0, l0, h1, l1;
            pack_hilo(x0, y0, h0, l0);
            pack_hilo(x1, y1, h1, l1);
            *(uint32_t*)(Oh + (size_t)r0 * N + col) = h0;
            *(uint32_t*)(Oh + (size_t)r1 * N + col) = h1;
            if (Ol) {
                *(uint32_t*)(Ol + (size_t)r0 * N + col) = l0;
                *(uint32_t*)(Ol + (size_t)r1 * N + col) = l1;
            }
        }
}

// ---------------- output projection: out = xn * wo^T (2-term fp16) ----------
__global__ __launch_bounds__(256, 2)
void o_gemm(float* __restrict__ C) {
    extern __shared__ char sm[];
    uint32_t sb = smem_to_u32(sm);
    int tid = threadIdx.x, lane = tid & 31, wid = tid >> 5;
    int wm = wid & 1, wn = wid >> 1;
    int row0 = blockIdx.y * 128, col0 = blockIdx.x * 128;

    float acc[4][4][4];
    #pragma unroll
    for (int i = 0; i < 4; ++i)
        #pragma unroll
        for (int j = 0; j < 4; ++j)
            #pragma unroll
            for (int q = 0; q < 4; ++q) acc[i][j][q] = 0.f;

    gemm_mainloop2(g_xn_h, g_xn_l, g_wo_h, row0, col0, DIMN, sb, acc);

    int mrow = row0 + wm * 64 + (lane >> 2);
    int ncol = col0 + wn * 32 + (lane & 3) * 2;
    #pragma unroll
    for (int mi = 0; mi < 4; ++mi)
        #pragma unroll
        for (int ni = 0; ni < 4; ++ni) {
            float* p0 = C + (size_t)(mrow + mi * 16) * DIMN + ncol + ni * 8;
            float* p1 = C + (size_t)(mrow + mi * 16 + 8) * DIMN + ncol + ni * 8;
            *(float2*)p0 = make_float2(acc[mi][ni][0], acc[mi][ni][1]);
            *(float2*)p1 = make_float2(acc[mi][ni][2], acc[mi][ni][3]);
        }
}

// ---------------- tensor-core flash attention --------------------------------
// QK 3-term (K frags via x4 covering k32); PV 1-term. Stage: Kh,Kl,V.
#define APITCH 272
#define ATILE  (64 * APITCH)     // 17408 bytes
#define QTILE  (128 * APITCH)    // 34816 bytes
#define KVSTAGE (3 * ATILE)

__device__ __forceinline__ void cp_kv(uint32_t dst, const __half* __restrict__ g,
                                      int b, int kvh, int row0) {
    int tid = threadIdx.x;
    #pragma unroll
    for (int j = 0; j < 4; ++j) {
        int lin = j * 256 + tid;
        int r = lin >> 4, c = lin & 15;
        const __half* s = g + (((size_t)(b * S_LEN + row0 + r)) * NKV + kvh) * HD + c * 8;
        cp16(dst + r * APITCH + c * 16, s);
    }
}

__global__ __launch_bounds__(256, 1)
void attn_kernel() {
    extern __shared__ char asm_[];
    uint32_t sb = smem_to_u32(asm_);
    const uint32_t smQh = sb;
    const uint32_t smQl = sb + QTILE;
    const uint32_t smKV = sb + 2 * QTILE;

    const int tid = threadIdx.x;
    const int lane = tid & 31, wid = tid >> 5;
    const int gid = lane >> 2, tig = lane & 3;
    const int qt = (int)gridDim.x - 1 - (int)blockIdx.x;   // largest-first
    const int q0 = qt * 128;
    const int h  = blockIdx.y;
    const int b  = blockIdx.z;
    const int kvh = h >> 2;
    const int m0 = wid * 16;
    const int nkt = 2 * (qt + 1);

    #pragma unroll
    for (int j = 0; j < 8; ++j) {
        int lin = j * 256 + tid;
        int r = lin >> 4, c = lin & 15;
        size_t go = (((size_t)(b * S_LEN + q0 + r)) * NH + h) * HD + c * 8;
        cp16(smQh + r * APITCH + c * 16, g_qh + go);
        cp16(smQl + r * APITCH + c * 16, g_ql + go);
    }
    cp_kv(smKV,             g_kh, b, kvh, 0);
    cp_kv(smKV + ATILE,     g_kl, b, kvh, 0);
    cp_kv(smKV + 2 * ATILE, g_v,  b, kvh, 0);
    asm volatile("cp.async.commit_group;" ::: "memory");
    {
        uint32_t st = smKV + KVSTAGE;
        cp_kv(st,             g_kh, b, kvh, 64);
        cp_kv(st + ATILE,     g_kl, b, kvh, 64);
        cp_kv(st + 2 * ATILE, g_v,  b, kvh, 64);
        asm volatile("cp.async.commit_group;" ::: "memory");
    }

    const int qg0 = q0 + m0 + gid;
    const int qg1 = qg0 + 8;
    const int qmax = q0 + m0 + 15;
    const int csq0 = (qg0 > 0) ? g_cs[b * S_LEN + qg0 - 1] : 0;
    const int csq1 = g_cs[b * S_LEN + qg1 - 1];

    float oacc[16][4];
    #pragma unroll
    for (int d = 0; d < 16; ++d)
        #pragma unroll
        for (int q = 0; q < 4; ++q) oacc[d][q] = 0.f;
    float mrow0 = -1e30f, mrow1 = -1e30f, lrow0 = 0.f, lrow1 = 0.f;

    for (int it = 0; it < nkt; ++it) {
        const int k0 = it * 64;
        if (it + 1 < nkt) asm volatile("cp.async.wait_group 1;" ::: "memory");
        else              asm volatile("cp.async.wait_group 0;" ::: "memory");
        __syncthreads();

        if (k0 <= qmax) {
            const uint32_t st  = smKV + (it & 1) * KVSTAGE;
            const uint32_t sKh = st, sKl = st + ATILE, sV = st + 2 * ATILE;

            float sacc[8][4];
            #pragma unroll
            for (int j = 0; j < 8; ++j)
                #pragma unroll
                for (int q = 0; q < 4; ++q) sacc[j][q] = 0.f;

            const uint32_t qoff = (m0 + (lane & 15)) * APITCH + (lane >> 4) * 16;
            const uint32_t koff = (lane & 7) * APITCH + (lane >> 3) * 16;  // x4: k32
            #pragma unroll
            for (int kk2 = 0; kk2 < 4; ++kk2) {
                uint32_t qh0[4], ql0[4], qh1[4], ql1[4];
                uint32_t qa = qoff + kk2 * 64;
                ldmx4(qh0, smQh + qa);
                ldmx4(ql0, smQl + qa);
                ldmx4(qh1, smQh + qa + 32);
                ldmx4(ql1, smQl + qa + 32);
                #pragma unroll
                for (int j = 0; j < 8; ++j) {
                    uint32_t kh[4], kl[4];
                    uint32_t ka = koff + j * 8 * APITCH + kk2 * 64;
                    ldmx4(kh, sKh + ka);
                    ldmx4(kl, sKl + ka);
                    mma16816(sacc[j], qh0, kh);
                    mma16816(sacc[j], qh0, kl);
                    mma16816(sacc[j], ql0, kh);
                    mma16816(sacc[j], qh1, kh + 2);
                    mma16816(sacc[j], qh1, kl + 2);
                    mma16816(sacc[j], ql1, kh + 2);
                }
            }

            if (k0 + 73 >= q0 + m0) {
                #pragma unroll
                for (int j = 0; j < 8; ++j) {
                    int kg0 = k0 + j * 8 + tig * 2;
                    int kg1 = kg0 + 1;
                    int bi0 = kg0 + 10; if (bi0 > S_LEN - 1) bi0 = S_LEN - 1;
                    int bi1 = kg1 + 10; if (bi1 > S_LEN - 1) bi1 = S_LEN - 1;
                    int ck0 = g_cs[b * S_LEN + bi0];
                    int ck1 = g_cs[b * S_LEN + bi1];
                    if (kg0 + 10 >= qg0 && ck0 - csq0 > 0) sacc[j][0] += 2.0f;
                    if (kg1 + 10 >= qg0 && ck1 - csq0 > 0) sacc[j][1] += 2.0f;
                    if (kg0 + 10 >= qg1 && ck0 - csq1 > 0) sacc[j][2] += 2.0f;
                    if (kg1 + 10 >= qg1 && ck1 - csq1 > 0) sacc[j][3] += 2.0f;
                }
            }
            if (k0 + 63 > qg0) {
                #pragma unroll
                for (int j = 0; j < 8; ++j) {
                    int kg0 = k0 + j * 8 + tig * 2;
                    int kg1 = kg0 + 1;
                    if (kg0 > qg0) sacc[j][0] = -1e9f;
                    if (kg1 > qg0) sacc[j][1] = -1e9f;
                    if (kg0 > qg1) sacc[j][2] = -1e9f;
                    if (kg1 > qg1) sacc[j][3] = -1e9f;
                }
            }

            float mx0 = -1e30f, mx1 = -1e30f;
            #pragma unroll
            for (int j = 0; j < 8; ++j) {
                mx0 = fmaxf(mx0, fmaxf(sacc[j][0], sacc[j][1]));
                mx1 = fmaxf(mx1, fmaxf(sacc[j][2], sacc[j][3]));
            }
            mx0 = fmaxf(mx0, __shfl_xor_sync(0xffffffffu, mx0, 1));
            mx0 = fmaxf(mx0, __shfl_xor_sync(0xffffffffu, mx0, 2));
            mx1 = fmaxf(mx1, __shfl_xor_sync(0xffffffffu, mx1, 1));
            mx1 = fmaxf(mx1, __shfl_xor_sync(0xffffffffu, mx1, 2));
            float mn0 = fmaxf(mrow0, mx0), mn1 = fmaxf(mrow1, mx1);
            float a0 = __expf(mrow0 - mn0), a1 = __expf(mrow1 - mn1);
            mrow0 = mn0; mrow1 = mn1;
            float sum0 = 0.f, sum1 = 0.f;
            #pragma unroll
            for (int j = 0; j < 8; ++j) {
                sacc[j][0] = __expf(sacc[j][0] - mn0); sum0 += sacc[j][0];
                sacc[j][1] = __expf(sacc[j][1] - mn0); sum0 += sacc[j][1];
                sacc[j][2] = __expf(sacc[j][2] - mn1); sum1 += sacc[j][2];
                sacc[j][3] = __expf(sacc[j][3] - mn1); sum1 += sacc[j][3];
            }
            sum0 += __shfl_xor_sync(0xffffffffu, sum0, 1);
            sum0 += __shfl_xor_sync(0xffffffffu, sum0, 2);
            sum1 += __shfl_xor_sync(0xffffffffu, sum1, 1);
            sum1 += __shfl_xor_sync(0xffffffffu, sum1, 2);
            lrow0 = lrow0 * a0 + sum0;
            lrow1 = lrow1 * a1 + sum1;
            #pragma unroll
            for (int d = 0; d < 16; ++d) {
                oacc[d][0] *= a0; oacc[d][1] *= a0;
                oacc[d][2] *= a1; oacc[d][3] *= a1;
            }

            // P fragments: single fp16
            uint32_t ph[4][4];
            #pragma unroll
            for (int t = 0; t < 4; ++t) {
                int j0 = 2 * t, j1 = 2 * t + 1;
                ph[t][0] = pack_h(sacc[j0][0], sacc[j0][1]);
                ph[t][1] = pack_h(sacc[j0][2], sacc[j0][3]);
                ph[t][2] = pack_h(sacc[j1][0], sacc[j1][1]);
                ph[t][3] = pack_h(sacc[j1][2], sacc[j1][3]);
            }

            // O += P V (1-term)
            const uint32_t voff = (lane & 15) * APITCH + (lane >> 4) * 16;
            #pragma unroll
            for (int t = 0; t < 4; ++t) {
                #pragma unroll
                for (int dn2 = 0; dn2 < 8; ++dn2) {
                    uint32_t vh[4];
                    ldmx4t(vh, sV + voff + t * 16 * APITCH + dn2 * 32);
                    mma16816(oacc[2 * dn2],     ph[t], vh);
                    mma16816(oacc[2 * dn2 + 1], ph[t], vh + 2);
                }
            }
        }
        __syncthreads();

        if (it + 2 < nkt) {
            uint32_t pst = smKV + (it & 1) * KVSTAGE;
            int row0 = (it + 2) * 64;
            cp_kv(pst,             g_kh, b, kvh, row0);
            cp_kv(pst + ATILE,     g_kl, b, kvh, row0);
            cp_kv(pst + 2 * ATILE, g_v,  b, kvh, row0);
            asm volatile("cp.async.commit_group;" ::: "memory");
        }
    }

    float il0 = 1.0f / lrow0, il1 = 1.0f / lrow1;
    size_t b0 = (((size_t)(b * S_LEN + qg0)) * NH + h) * HD + tig * 2;
    size_t b1 = (((size_t)(b * S_LEN + qg1)) * NH + h) * HD + tig * 2;
    #pragma unroll
    for (int d = 0; d < 16; ++d) {
        *(uint32_t*)(g_ao + b0 + d * 8) = pack_h(oacc[d][0] * il0, oacc[d][1] * il0);
        *(uint32_t*)(g_ao + b1 + d * 8) = pack_h(oacc[d][2] * il1, oacc[d][3] * il1);
    }
}

// ---------------- launch ----------------------------------------------------
extern "C" void kernel_launch(void* const* d_in, const int* in_sizes, int n_in,
                              void* d_out, int out_size) {
    const float* x      = (const float*)d_in[0];
    const float* freqs  = (const float*)d_in[2];
    const int*   labels = (const int*)d_in[4];
    const float* wq     = (const float*)d_in[5];
    const float* wk     = (const float*)d_in[6];
    const float* wv     = (const float*)d_in[7];
    const float* wo     = (const float*)d_in[8];
    const float* ln1w   = (const float*)d_in[9];
    const float* ln1b   = (const float*)d_in[10];
    const float* ln2w   = (const float*)d_in[11];
    const float* ln2b   = (const float*)d_in[12];
    float* out = (float*)d_out;

    __half *xnh, *xnl, *ao;
    cudaGetSymbolAddress((void**)&xnh, g_xn_h);
    cudaGetSymbolAddress((void**)&xnl, g_xn_l);
    cudaGetSymbolAddress((void**)&ao,  g_ao);

    split_all<<<(TOT_F4 + 255) / 256, 256>>>(wq, wk, wv, wo);
    ln_kernel<<<ROWS, 256>>>(x, ln1w, ln1b, xnh, xnl);
    cumsum_kernel<<<2, 1024>>>(labels);

    size_t gemm_smem = 3 * STAGE2_B;   // 92160 (covers 2-stage 3-term: 81920)
    cudaFuncSetAttribute(qkv_gemm, cudaFuncAttributeMaxDynamicSharedMemorySize, (int)gemm_smem);
    cudaFuncSetAttribute(o_gemm, cudaFuncAttributeMaxDynamicSharedMemorySize, (int)gemm_smem);

    const float qscale = 0.08838834764831845f;   // 1/sqrt(128)
    qkv_gemm<<<dim3(24, ROWS / 128), 256, gemm_smem>>>(freqs, qscale);

    size_t attn_smem = 2 * QTILE + 2 * KVSTAGE;   // 174080
    cudaFuncSetAttribute(attn_kernel, cudaFuncAttributeMaxDynamicSharedMemorySize,
                         (int)attn_smem);
    attn_kernel<<<dim3(S_LEN / 128, NH, 2), 256, attn_smem>>>();

    ln_kernel_h<<<ROWS, 256>>>(ao, ln2w, ln2b, xnh, xnl);
    o_gemm<<<dim3(DIMN / 128, ROWS / 128), 256, gemm_smem>>>(out);
}

// round 13
// speedup vs baseline: 1.0200x; 1.0200x over previous
#include <cuda_runtime.h>
#include <cuda_fp16.h>
#include <math.h>
#include <stdint.h>

#define S_LEN 2048
#define DIMN  2048
#define NH    16
#define NKV   4
#define HD    128
#define ROWS  4096   // B*S

// ---------------- scratch (device globals; no allocation allowed) ----------
__device__ __half g_xn_h[ROWS * DIMN];
__device__ __half g_xn_l[ROWS * DIMN];
__device__ __half g_wq_h[DIMN * DIMN];
__device__ __half g_wq_l[DIMN * DIMN];
__device__ __half g_wk_h[512 * DIMN];
__device__ __half g_wk_l[512 * DIMN];
__device__ __half g_wv_h[512 * DIMN];    // single fp16 (2-term V proj)
__device__ __half g_wo_h[DIMN * DIMN];   // single fp16 (2-term o_gemm)
__device__ __half g_qh[ROWS * DIMN];  // roped+scaled Q hi/lo
__device__ __half g_ql[ROWS * DIMN];
__device__ __half g_kh[ROWS * 512];   // roped K hi/lo
__device__ __half g_kl[ROWS * 512];
__device__ __half g_v [ROWS * 512];   // V single fp16
__device__ __half g_ao[ROWS * DIMN];  // attention output, fp16
__device__ int   g_cs[2 * S_LEN];     // per-batch inclusive cumsum of labels

// ---------------- helpers ----------------------------------------------------
__device__ __forceinline__ uint32_t smem_to_u32(const void* p) {
    uint32_t a;
    asm("{ .reg .u64 t; cvta.to.shared.u64 t, %1; cvt.u32.u64 %0, t; }" : "=r"(a) : "l"(p));
    return a;
}
__device__ __forceinline__ void ldmx4(uint32_t* r, uint32_t addr) {
    asm volatile("ldmatrix.sync.aligned.m8n8.x4.shared.b16 {%0,%1,%2,%3}, [%4];"
        : "=r"(r[0]), "=r"(r[1]), "=r"(r[2]), "=r"(r[3]) : "r"(addr));
}
__device__ __forceinline__ void ldmx4t(uint32_t* r, uint32_t addr) {
    asm volatile("ldmatrix.sync.aligned.m8n8.x4.trans.shared.b16 {%0,%1,%2,%3}, [%4];"
        : "=r"(r[0]), "=r"(r[1]), "=r"(r[2]), "=r"(r[3]) : "r"(addr));
}
__device__ __forceinline__ void mma16816(float* c, const uint32_t* a, const uint32_t* b) {
    asm volatile(
        "mma.sync.aligned.m16n8k16.row.col.f32.f16.f16.f32 "
        "{%0,%1,%2,%3}, {%4,%5,%6,%7}, {%8,%9}, {%0,%1,%2,%3};"
        : "+f"(c[0]), "+f"(c[1]), "+f"(c[2]), "+f"(c[3])
        : "r"(a[0]), "r"(a[1]), "r"(a[2]), "r"(a[3]), "r"(b[0]), "r"(b[1]));
}
__device__ __forceinline__ void cp16(uint32_t d, const void* s) {
    asm volatile("cp.async.ca.shared.global [%0], [%1], 16;" :: "r"(d), "l"(s));
}
__device__ __forceinline__ void pack_hilo(float x, float y, uint32_t& h, uint32_t& l) {
    __half2 hb = __floats2half2_rn(x, y);
    float rx = x - __low2float(hb);
    float ry = y - __high2float(hb);
    __half2 lb = __floats2half2_rn(rx, ry);
    h = *(uint32_t*)&hb;
    l = *(uint32_t*)&lb;
}
__device__ __forceinline__ uint32_t pack_h(float x, float y) {
    __half2 hb = __floats2half2_rn(x, y);
    return *(uint32_t*)&hb;
}

// ---------------- cumsum of seizure labels (per batch) ---------------------
__global__ void cumsum_kernel(const int* __restrict__ labels) {
    __shared__ int bufA[S_LEN], bufB[S_LEN];
    int b = blockIdx.x;
    for (int i = threadIdx.x; i < S_LEN; i += blockDim.x)
        bufA[i] = labels[b * S_LEN + i];
    __syncthreads();
    int* src = bufA; int* dst = bufB;
    for (int off = 1; off < S_LEN; off <<= 1) {
        for (int i = threadIdx.x; i < S_LEN; i += blockDim.x)
            dst[i] = src[i] + (i >= off ? src[i - off] : 0);
        __syncthreads();
        int* t = src; src = dst; dst = t;
    }
    for (int i = threadIdx.x; i < S_LEN; i += blockDim.x)
        g_cs[b * S_LEN + i] = src[i];
}

// ---------------- merged weight split (all 4 weights in one launch) ---------
#define WQ_F4 1048576   // 2048*2048/4
#define WK_F4 262144    // 512*2048/4
#define WV_F4 262144
#define WO_F4 1048576
#define TOT_F4 (WQ_F4 + WK_F4 + WV_F4 + WO_F4)

__global__ void split_all(const float* __restrict__ wq, const float* __restrict__ wk,
                          const float* __restrict__ wv, const float* __restrict__ wo) {
    int i = blockIdx.x * blockDim.x + threadIdx.x;
    if (i >= TOT_F4) return;
    const float* src; __half *hi, *lo; int j = i;
    if (j < WQ_F4) { src = wq; hi = g_wq_h; lo = g_wq_l; }
    else if ((j -= WQ_F4) < WK_F4) { src = wk; hi = g_wk_h; lo = g_wk_l; }
    else if ((j -= WK_F4) < WV_F4) { src = wv; hi = g_wv_h; lo = nullptr; }
    else { j -= WV_F4; src = wo; hi = g_wo_h; lo = nullptr; }
    float4 v = ((const float4*)src)[j];
    uint32_t h01, h23, l01, l23;
    pack_hilo(v.x, v.y, h01, l01);
    pack_hilo(v.z, v.w, h23, l23);
    *(uint2*)(hi + (size_t)j * 4) = make_uint2(h01, h23);
    if (lo) *(uint2*)(lo + (size_t)j * 4) = make_uint2(l01, l23);
}

// ---------------- layernorm (fp32 in) -> fp16 hi/lo --------------------------
__global__ void ln_kernel(const float* __restrict__ in, const float* __restrict__ w,
                          const float* __restrict__ bvec,
                          __half* __restrict__ oh, __half* __restrict__ ol) {
    int row = blockIdx.x;
    const float* x = in + (size_t)row * DIMN;
    int tid = threadIdx.x;

    float4 v0 = *(const float4*)(x + tid * 4);
    float4 v1 = *(const float4*)(x + 1024 + tid * 4);
    float s  = v0.x + v0.y + v0.z + v0.w + v1.x + v1.y + v1.z + v1.w;
    float ss = v0.x*v0.x + v0.y*v0.y + v0.z*v0.z + v0.w*v0.w
             + v1.x*v1.x + v1.y*v1.y + v1.z*v1.z + v1.w*v1.w;
    #pragma unroll
    for (int off = 16; off; off >>= 1) {
        s  += __shfl_xor_sync(0xffffffffu, s,  off);
        ss += __shfl_xor_sync(0xffffffffu, ss, off);
    }
    __shared__ float rs[8], rss[8];
    __shared__ float s_mu, s_rstd;
    int wid = tid >> 5, lane = tid & 31;
    if (!lane) { rs[wid] = s; rss[wid] = ss; }
    __syncthreads();
    if (tid == 0) {
        float S = 0.f, SS = 0.f;
        #pragma unroll
        for (int i = 0; i < 8; ++i) { S += rs[i]; SS += rss[i]; }
        float mu = S / DIMN;
        s_mu = mu;
        s_rstd = rsqrtf(SS / DIMN - mu * mu + 1e-5f);
    }
    __syncthreads();
    float mu = s_mu, rstd = s_rstd;

    size_t base = (size_t)row * DIMN;
    #pragma unroll
    for (int half = 0; half < 2; ++half) {
        int off = half * 1024 + tid * 4;
        float4 v = half ? v1 : v0;
        float4 w4 = *(const float4*)(w + off);
        float4 b4 = *(const float4*)(bvec + off);
        float4 r;
        r.x = (v.x - mu) * rstd * w4.x + b4.x;
        r.y = (v.y - mu) * rstd * w4.y + b4.y;
        r.z = (v.z - mu) * rstd * w4.z + b4.z;
        r.w = (v.w - mu) * rstd * w4.w + b4.w;
        uint32_t h01, h23, l01, l23;
        pack_hilo(r.x, r.y, h01, l01);
        pack_hilo(r.z, r.w, h23, l23);
        *(uint2*)(oh + base + off) = make_uint2(h01, h23);
        *(uint2*)(ol + base + off) = make_uint2(l01, l23);
    }
}

// ---------------- layernorm (fp16 in) -> fp16 hi/lo --------------------------
__global__ void ln_kernel_h(const __half* __restrict__ in, const float* __restrict__ w,
                            const float* __restrict__ bvec,
                            __half* __restrict__ oh, __half* __restrict__ ol) {
    int row = blockIdx.x;
    const __half* x = in + (size_t)row * DIMN;
    int tid = threadIdx.x;

    uint4 u = *(const uint4*)(x + tid * 8);
    __half2 hv[4] = {*(__half2*)&u.x, *(__half2*)&u.y, *(__half2*)&u.z, *(__half2*)&u.w};
    float e[8];
    #pragma unroll
    for (int i = 0; i < 4; ++i) {
        float2 f = __half22float2(hv[i]);
        e[2 * i] = f.x; e[2 * i + 1] = f.y;
    }
    float s = 0.f, ss = 0.f;
    #pragma unroll
    for (int i = 0; i < 8; ++i) { s += e[i]; ss += e[i] * e[i]; }
    #pragma unroll
    for (int off = 16; off; off >>= 1) {
        s  += __shfl_xor_sync(0xffffffffu, s,  off);
        ss += __shfl_xor_sync(0xffffffffu, ss, off);
    }
    __shared__ float rs[8], rss[8];
    __shared__ float s_mu, s_rstd;
    int wid = tid >> 5, lane = tid & 31;
    if (!lane) { rs[wid] = s; rss[wid] = ss; }
    __syncthreads();
    if (tid == 0) {
        float S = 0.f, SS = 0.f;
        #pragma unroll
        for (int i = 0; i < 8; ++i) { S += rs[i]; SS += rss[i]; }
        float mu = S / DIMN;
        s_mu = mu;
        s_rstd = rsqrtf(SS / DIMN - mu * mu + 1e-5f);
    }
    __syncthreads();
    float mu = s_mu, rstd = s_rstd;

    size_t base = (size_t)row * DIMN + tid * 8;
    uint32_t hw[4], lw[4];
    #pragma unroll
    for (int i = 0; i < 4; ++i) {
        int off = tid * 8 + 2 * i;
        float2 w2 = *(const float2*)(w + off);
        float2 b2 = *(const float2*)(bvec + off);
        float rx = (e[2 * i]     - mu) * rstd * w2.x + b2.x;
        float ry = (e[2 * i + 1] - mu) * rstd * w2.y + b2.y;
        pack_hilo(rx, ry, hw[i], lw[i]);
    }
    *(uint4*)(oh + base) = make_uint4(hw[0], hw[1], hw[2], hw[3]);
    *(uint4*)(ol + base) = make_uint4(lw[0], lw[1], lw[2], lw[3]);
}

// ---------------- shared GEMM mainloops --------------------------------------
#define PITCH 80
#define TILE_B (128 * PITCH)
#define STAGE_B (4 * TILE_B)     // 2-stage layout (both mainloops)

__device__ __forceinline__ void cp_tile(uint32_t sdst, const __half* __restrict__ g,
                                        int row0, int K, int k0) {
    int tid = threadIdx.x;
    const char* gb = (const char*)(g + (size_t)row0 * K + k0);
    size_t rb = (size_t)K * 2;
    #pragma unroll
    for (int j = 0; j < 2; ++j) {
        int lin = j * 256 + tid;
        int r = lin >> 2, c = lin & 3;
        cp16(sdst + r * PITCH + c * 16, gb + (size_t)r * rb + c * 16);
    }
}

// 3-term mainloop (2 stages): D += Ah Bh + Ah Bl + Al Bh
__device__ __forceinline__ void gemm_mainloop(
        const __half* __restrict__ Ah, const __half* __restrict__ Al,
        const __half* __restrict__ Bh, const __half* __restrict__ Bl,
        int row0, int col0, int K, uint32_t sb, float acc[4][4][4]) {
    int tid = threadIdx.x, lane = tid & 31, wid = tid >> 5;
    int wm = wid & 1, wn = wid >> 1;

    const int nst = K >> 5;
    cp_tile(sb,              Ah, row0, K, 0);
    cp_tile(sb + TILE_B,     Al, row0, K, 0);
    cp_tile(sb + 2 * TILE_B, Bh, col0, K, 0);
    cp_tile(sb + 3 * TILE_B, Bl, col0, K, 0);
    asm volatile("cp.async.commit_group;" ::: "memory");

    for (int i = 0; i < nst; ++i) {
        asm volatile("cp.async.wait_group 0;" ::: "memory");
        __syncthreads();

        if (i + 1 < nst) {
            uint32_t pst = sb + ((i + 1) & 1) * STAGE_B;
            int k0 = (i + 1) << 5;
            cp_tile(pst,              Ah, row0, K, k0);
            cp_tile(pst + TILE_B,     Al, row0, K, k0);
            cp_tile(pst + 2 * TILE_B, Bh, col0, K, k0);
            cp_tile(pst + 3 * TILE_B, Bl, col0, K, k0);
            asm volatile("cp.async.commit_group;" ::: "memory");
        }

        uint32_t st = sb + (i & 1) * STAGE_B;
        uint32_t bh[4][4], bl[4][4];
        uint32_t bbase = st + 2 * TILE_B + (wn * 32 + (lane & 7)) * PITCH
                       + ((lane >> 3) & 1) * 16 + (lane >> 4) * 32;
        #pragma unroll
        for (int ni = 0; ni < 4; ++ni) ldmx4(bh[ni], bbase + ni * 8 * PITCH);
        #pragma unroll
        for (int ni = 0; ni < 4; ++ni) ldmx4(bl[ni], bbase + TILE_B + ni * 8 * PITCH);

        uint32_t abase = st + (wm * 64 + (lane & 15)) * PITCH + (lane >> 4) * 16;
        #pragma unroll
        for (int mi = 0; mi < 4; ++mi) {
            uint32_t ah0[4], al0[4], ah1[4], al1[4];
            uint32_t am = abase + mi * 16 * PITCH;
            ldmx4(ah0, am);
            ldmx4(al0, am + TILE_B);
            ldmx4(ah1, am + 32);
            ldmx4(al1, am + TILE_B + 32);
            #pragma unroll
            for (int ni = 0; ni < 4; ++ni) {
                mma16816(acc[mi][ni], ah0, bh[ni]);
                mma16816(acc[mi][ni], ah0, bl[ni]);
                mma16816(acc[mi][ni], al0, bh[ni]);
            }
            #pragma unroll
            for (int ni = 0; ni < 4; ++ni) {
                mma16816(acc[mi][ni], ah1, bh[ni] + 2);
                mma16816(acc[mi][ni], ah1, bl[ni] + 2);
                mma16816(acc[mi][ni], al1, bh[ni] + 2);
            }
        }
    }
    __syncthreads();
}

// 2-term mainloop (2 stages): D += Ah Bh + Al Bh  (B single fp16)
__device__ __forceinline__ void gemm_mainloop2(
        const __half* __restrict__ Ah, const __half* __restrict__ Al,
        const __half* __restrict__ Bh,
        int row0, int col0, int K, uint32_t sb, float acc[4][4][4]) {
    int tid = threadIdx.x, lane = tid & 31, wid = tid >> 5;
    int wm = wid & 1, wn = wid >> 1;

    const int nst = K >> 5;
    cp_tile(sb,              Ah, row0, K, 0);
    cp_tile(sb + TILE_B,     Al, row0, K, 0);
    cp_tile(sb + 2 * TILE_B, Bh, col0, K, 0);
    asm volatile("cp.async.commit_group;" ::: "memory");

    for (int i = 0; i < nst; ++i) {
        asm volatile("cp.async.wait_group 0;" ::: "memory");
        __syncthreads();

        if (i + 1 < nst) {
            uint32_t pst = sb + ((i + 1) & 1) * STAGE_B;
            int k0 = (i + 1) << 5;
            cp_tile(pst,              Ah, row0, K, k0);
            cp_tile(pst + TILE_B,     Al, row0, K, k0);
            cp_tile(pst + 2 * TILE_B, Bh, col0, K, k0);
            asm volatile("cp.async.commit_group;" ::: "memory");
        }

        uint32_t st = sb + (i & 1) * STAGE_B;
        uint32_t bh[4][4];
        uint32_t bbase = st + 2 * TILE_B + (wn * 32 + (lane & 7)) * PITCH
                       + ((lane >> 3) & 1) * 16 + (lane >> 4) * 32;
        #pragma unroll
        for (int ni = 0; ni < 4; ++ni) ldmx4(bh[ni], bbase + ni * 8 * PITCH);

        uint32_t abase = st + (wm * 64 + (lane & 15)) * PITCH + (lane >> 4) * 16;
        #pragma unroll
        for (int mi = 0; mi < 4; ++mi) {
            uint32_t ah0[4], al0[4], ah1[4], al1[4];
            uint32_t am = abase + mi * 16 * PITCH;
            ldmx4(ah0, am);
            ldmx4(al0, am + TILE_B);
            ldmx4(ah1, am + 32);
            ldmx4(al1, am + TILE_B + 32);
            #pragma unroll
            for (int ni = 0; ni < 4; ++ni) {
                mma16816(acc[mi][ni], ah0, bh[ni]);
                mma16816(acc[mi][ni], al0, bh[ni]);
            }
            #pragma unroll
            for (int ni = 0; ni < 4; ++ni) {
                mma16816(acc[mi][ni], ah1, bh[ni] + 2);
                mma16816(acc[mi][ni], al1, bh[ni] + 2);
            }
        }
    }
    __syncthreads();
}

// ---------------- merged QKV projection (one launch) ------------------------
// blockIdx.x: [0,16) -> Q (rope+scale, 3-term), [16,20) -> K (rope, 3-term),
//             [20,24) -> V (2-term, single fp16 out)
__global__ __launch_bounds__(256, 2)
void qkv_gemm(const float* __restrict__ fr, float qscale) {
    extern __shared__ char sm[];
    uint32_t sb = smem_to_u32(sm);
    int bx = blockIdx.x;
    int tid = threadIdx.x, lane = tid & 31, wid = tid >> 5;
    int wm = wid & 1, wn = wid >> 1;
    int row0 = blockIdx.y * 128;

    float acc[4][4][4];
    #pragma unroll
    for (int i = 0; i < 4; ++i)
        #pragma unroll
        for (int j = 0; j < 4; ++j)
            #pragma unroll
            for (int q = 0; q < 4; ++q) acc[i][j][q] = 0.f;

    __half *Oh, *Ol;
    int N, col0, do_rope;
    float scale;
    if (bx < 16) {
        Oh = g_qh; Ol = g_ql;
        N = DIMN; col0 = bx * 128; do_rope = 1; scale = qscale;
        gemm_mainloop(g_xn_h, g_xn_l, g_wq_h, g_wq_l, row0, col0, DIMN, sb, acc);
    } else if (bx < 20) {
        Oh = g_kh; Ol = g_kl;
        N = 512; col0 = (bx - 16) * 128; do_rope = 1; scale = 1.0f;
        gemm_mainloop(g_xn_h, g_xn_l, g_wk_h, g_wk_l, row0, col0, DIMN, sb, acc);
    } else {
        Oh = g_v; Ol = nullptr;
        N = 512; col0 = (bx - 20) * 128; do_rope = 0; scale = 1.0f;
        gemm_mainloop2(g_xn_h, g_xn_l, g_wv_h, row0, col0, DIMN, sb, acc);
    }

    int mrow = row0 + wm * 64 + (lane >> 2);
    int ncol = col0 + wn * 32 + (lane & 3) * 2;
    #pragma unroll
    for (int mi = 0; mi < 4; ++mi)
        #pragma unroll
        for (int ni = 0; ni < 4; ++ni) {
            int col = ncol + ni * 8;
            int r0 = mrow + mi * 16, r1 = r0 + 8;
            float x0 = acc[mi][ni][0], y0 = acc[mi][ni][1];
            float x1 = acc[mi][ni][2], y1 = acc[mi][ni][3];
            if (do_rope) {
                int fi = (col & 127) >> 1;
                int s0 = r0 & (S_LEN - 1), s1 = r1 & (S_LEN - 1);
                float c0 = fr[(s0 * 64 + fi) * 2], n0 = fr[(s0 * 64 + fi) * 2 + 1];
                float c1 = fr[(s1 * 64 + fi) * 2], n1 = fr[(s1 * 64 + fi) * 2 + 1];
                float tx0 = (x0 * c0 - y0 * n0) * scale;
                float ty0 = (x0 * n0 + y0 * c0) * scale;
                float tx1 = (x1 * c1 - y1 * n1) * scale;
                float ty1 = (x1 * n1 + y1 * c1) * scale;
                x0 = tx0; y0 = ty0; x1 = tx1; y1 = ty1;
            }
            uint32_t h0, l0, h1, l1;
            pack_hilo(x0, y0, h0, l0);
            pack_hilo(x1, y1, h1, l1);
            *(uint32_t*)(Oh + (size_t)r0 * N + col) = h0;
            *(uint32_t*)(Oh + (size_t)r1 * N + col) = h1;
            if (Ol) {
                *(uint32_t*)(Ol + (size_t)r0 * N + col) = l0;
                *(uint32_t*)(Ol + (size_t)r1 * N + col) = l1;
            }
        }
}

// ---------------- output projection: out = xn * wo^T (2-term fp16) ----------
__global__ __launch_bounds__(256, 2)
void o_gemm(float* __restrict__ C) {
    extern __shared__ char sm[];
    uint32_t sb = smem_to_u32(sm);
    int tid = threadIdx.x, lane = tid & 31, wid = tid >> 5;
    int wm = wid & 1, wn = wid >> 1;
    int row0 = blockIdx.y * 128, col0 = blockIdx.x * 128;

    float acc[4][4][4];
    #pragma unroll
    for (int i = 0; i < 4; ++i)
        #pragma unroll
        for (int j = 0; j < 4; ++j)
            #pragma unroll
            for (int q = 0; q < 4; ++q) acc[i][j][q] = 0.f;

    gemm_mainloop2(g_xn_h, g_xn_l, g_wo_h, row0, col0, DIMN, sb, acc);

    int mrow = row0 + wm * 64 + (lane >> 2);
    int ncol = col0 + wn * 32 + (lane & 3) * 2;
    #pragma unroll
    for (int mi = 0; mi < 4; ++mi)
        #pragma unroll
        for (int ni = 0; ni < 4; ++ni) {
            float* p0 = C + (size_t)(mrow + mi * 16) * DIMN + ncol + ni * 8;
            float* p1 = C + (size_t)(mrow + mi * 16 + 8) * DIMN + ncol + ni * 8;
            *(float2*)p0 = make_float2(acc[mi][ni][0], acc[mi][ni][1]);
            *(float2*)p1 = make_float2(acc[mi][ni][2], acc[mi][ni][3]);
        }
}

// ---------------- tensor-core flash attention --------------------------------
// QK 3-term (K frags via x4 covering k32); PV 1-term. Stage: Kh,Kl,V.
#define APITCH 272
#define ATILE  (64 * APITCH)     // 17408 bytes
#define QTILE  (128 * APITCH)    // 34816 bytes
#define KVSTAGE (3 * ATILE)

__device__ __forceinline__ void cp_kv(uint32_t dst, const __half* __restrict__ g,
                                      int b, int kvh, int row0) {
    int tid = threadIdx.x;
    #pragma unroll
    for (int j = 0; j < 4; ++j) {
        int lin = j * 256 + tid;
        int r = lin >> 4, c = lin & 15;
        const __half* s = g + (((size_t)(b * S_LEN + row0 + r)) * NKV + kvh) * HD + c * 8;
        cp16(dst + r * APITCH + c * 16, s);
    }
}

__global__ __launch_bounds__(256, 1)
void attn_kernel() {
    extern __shared__ char asm_[];
    uint32_t sb = smem_to_u32(asm_);
    const uint32_t smQh = sb;
    const uint32_t smQl = sb + QTILE;
    const uint32_t smKV = sb + 2 * QTILE;

    const int tid = threadIdx.x;
    const int lane = tid & 31, wid = tid >> 5;
    const int gid = lane >> 2, tig = lane & 3;
    const int qt = (int)gridDim.x - 1 - (int)blockIdx.x;   // largest-first
    const int q0 = qt * 128;
    const int h  = blockIdx.y;
    const int b  = blockIdx.z;
    const int kvh = h >> 2;
    const int m0 = wid * 16;
    const int nkt = 2 * (qt + 1);

    #pragma unroll
    for (int j = 0; j < 8; ++j) {
        int lin = j * 256 + tid;
        int r = lin >> 4, c = lin & 15;
        size_t go = (((size_t)(b * S_LEN + q0 + r)) * NH + h) * HD + c * 8;
        cp16(smQh + r * APITCH + c * 16, g_qh + go);
        cp16(smQl + r * APITCH + c * 16, g_ql + go);
    }
    cp_kv(smKV,             g_kh, b, kvh, 0);
    cp_kv(smKV + ATILE,     g_kl, b, kvh, 0);
    cp_kv(smKV + 2 * ATILE, g_v,  b, kvh, 0);
    asm volatile("cp.async.commit_group;" ::: "memory");
    {
        uint32_t st = smKV + KVSTAGE;
        cp_kv(st,             g_kh, b, kvh, 64);
        cp_kv(st + ATILE,     g_kl, b, kvh, 64);
        cp_kv(st + 2 * ATILE, g_v,  b, kvh, 64);
        asm volatile("cp.async.commit_group;" ::: "memory");
    }

    const int qg0 = q0 + m0 + gid;
    const int qg1 = qg0 + 8;
    const int qmax = q0 + m0 + 15;
    const int csq0 = (qg0 > 0) ? g_cs[b * S_LEN + qg0 - 1] : 0;
    const int csq1 = g_cs[b * S_LEN + qg1 - 1];

    float oacc[16][4];
    #pragma unroll
    for (int d = 0; d < 16; ++d)
        #pragma unroll
        for (int q = 0; q < 4; ++q) oacc[d][q] = 0.f;
    float mrow0 = -1e30f, mrow1 = -1e30f, lrow0 = 0.f, lrow1 = 0.f;

    for (int it = 0; it < nkt; ++it) {
        const int k0 = it * 64;
        if (it + 1 < nkt) asm volatile("cp.async.wait_group 1;" ::: "memory");
        else              asm volatile("cp.async.wait_group 0;" ::: "memory");
        __syncthreads();

        if (k0 <= qmax) {
            const uint32_t st  = smKV + (it & 1) * KVSTAGE;
            const uint32_t sKh = st, sKl = st + ATILE, sV = st + 2 * ATILE;

            float sacc[8][4];
            #pragma unroll
            for (int j = 0; j < 8; ++j)
                #pragma unroll
                for (int q = 0; q < 4; ++q) sacc[j][q] = 0.f;

            const uint32_t qoff = (m0 + (lane & 15)) * APITCH + (lane >> 4) * 16;
            const uint32_t koff = (lane & 7) * APITCH + (lane >> 3) * 16;  // x4: k32
            #pragma unroll
            for (int kk2 = 0; kk2 < 4; ++kk2) {
                uint32_t qh0[4], ql0[4], qh1[4], ql1[4];
                uint32_t qa = qoff + kk2 * 64;
                ldmx4(qh0, smQh + qa);
                ldmx4(ql0, smQl + qa);
                ldmx4(qh1, smQh + qa + 32);
                ldmx4(ql1, smQl + qa + 32);
                #pragma unroll
                for (int j = 0; j < 8; ++j) {
                    uint32_t kh[4], kl[4];
                    uint32_t ka = koff + j * 8 * APITCH + kk2 * 64;
                    ldmx4(kh, sKh + ka);
                    ldmx4(kl, sKl + ka);
                    mma16816(sacc[j], qh0, kh);
                    mma16816(sacc[j], qh0, kl);
                    mma16816(sacc[j], ql0, kh);
                    mma16816(sacc[j], qh1, kh + 2);
                    mma16816(sacc[j], qh1, kl + 2);
                    mma16816(sacc[j], ql1, kh + 2);
                }
            }

            if (k0 + 73 >= q0 + m0) {
                #pragma unroll
                for (int j = 0; j < 8; ++j) {
                    int kg0 = k0 + j * 8 + tig * 2;
                    int kg1 = kg0 + 1;
                    int bi0 = kg0 + 10; if (bi0 > S_LEN - 1) bi0 = S_LEN - 1;
                    int bi1 = kg1 + 10; if (bi1 > S_LEN - 1) bi1 = S_LEN - 1;
                    int ck0 = g_cs[b * S_LEN + bi0];
                    int ck1 = g_cs[b * S_LEN + bi1];
                    if (kg0 + 10 >= qg0 && ck0 - csq0 > 0) sacc[j][0] += 2.0f;
                    if (kg1 + 10 >= qg0 && ck1 - csq0 > 0) sacc[j][1] += 2.0f;
                    if (kg0 + 10 >= qg1 && ck0 - csq1 > 0) sacc[j][2] += 2.0f;
                    if (kg1 + 10 >= qg1 && ck1 - csq1 > 0) sacc[j][3] += 2.0f;
                }
            }
            if (k0 + 63 > qg0) {
                #pragma unroll
                for (int j = 0; j < 8; ++j) {
                    int kg0 = k0 + j * 8 + tig * 2;
                    int kg1 = kg0 + 1;
                    if (kg0 > qg0) sacc[j][0] = -1e9f;
                    if (kg1 > qg0) sacc[j][1] = -1e9f;
                    if (kg0 > qg1) sacc[j][2] = -1e9f;
                    if (kg1 > qg1) sacc[j][3] = -1e9f;
                }
            }

            float mx0 = -1e30f, mx1 = -1e30f;
            #pragma unroll
            for (int j = 0; j < 8; ++j) {
                mx0 = fmaxf(mx0, fmaxf(sacc[j][0], sacc[j][1]));
                mx1 = fmaxf(mx1, fmaxf(sacc[j][2], sacc[j][3]));
            }
            mx0 = fmaxf(mx0, __shfl_xor_sync(0xffffffffu, mx0, 1));
            mx0 = fmaxf(mx0, __shfl_xor_sync(0xffffffffu, mx0, 2));
            mx1 = fmaxf(mx1, __shfl_xor_sync(0xffffffffu, mx1, 1));
            mx1 = fmaxf(mx1, __shfl_xor_sync(0xffffffffu, mx1, 2));
            float mn0 = fmaxf(mrow0, mx0), mn1 = fmaxf(mrow1, mx1);
            float a0 = __expf(mrow0 - mn0), a1 = __expf(mrow1 - mn1);
            mrow0 = mn0; mrow1 = mn1;
            float sum0 = 0.f, sum1 = 0.f;
            #pragma unroll
            for (int j = 0; j < 8; ++j) {
                sacc[j][0] = __expf(sacc[j][0] - mn0); sum0 += sacc[j][0];
                sacc[j][1] = __expf(sacc[j][1] - mn0); sum0 += sacc[j][1];
                sacc[j][2] = __expf(sacc[j][2] - mn1); sum1 += sacc[j][2];
                sacc[j][3] = __expf(sacc[j][3] - mn1); sum1 += sacc[j][3];
            }
            sum0 += __shfl_xor_sync(0xffffffffu, sum0, 1);
            sum0 += __shfl_xor_sync(0xffffffffu, sum0, 2);
            sum1 += __shfl_xor_sync(0xffffffffu, sum1, 1);
            sum1 += __shfl_xor_sync(0xffffffffu, sum1, 2);
            lrow0 = lrow0 * a0 + sum0;
            lrow1 = lrow1 * a1 + sum1;
            #pragma unroll
            for (int d = 0; d < 16; ++d) {
                oacc[d][0] *= a0; oacc[d][1] *= a0;
                oacc[d][2] *= a1; oacc[d][3] *= a1;
            }

            uint32_t ph[4][4];
            #pragma unroll
            for (int t = 0; t < 4; ++t) {
                int j0 = 2 * t, j1 = 2 * t + 1;
                ph[t][0] = pack_h(sacc[j0][0], sacc[j0][1]);
                ph[t][1] = pack_h(sacc[j0][2], sacc[j0][3]);
                ph[t][2] = pack_h(sacc[j1][0], sacc[j1][1]);
                ph[t][3] = pack_h(sacc[j1][2], sacc[j1][3]);
            }

            const uint32_t voff = (lane & 15) * APITCH + (lane >> 4) * 16;
            #pragma unroll
            for (int t = 0; t < 4; ++t) {
                #pragma unroll
                for (int dn2 = 0; dn2 < 8; ++dn2) {
                    uint32_t vh[4];
                    ldmx4t(vh, sV + voff + t * 16 * APITCH + dn2 * 32);
                    mma16816(oacc[2 * dn2],     ph[t], vh);
                    mma16816(oacc[2 * dn2 + 1], ph[t], vh + 2);
                }
            }
        }
        __syncthreads();

        if (it + 2 < nkt) {
            uint32_t pst = smKV + (it & 1) * KVSTAGE;
            int row0 = (it + 2) * 64;
            cp_kv(pst,             g_kh, b, kvh, row0);
            cp_kv(pst + ATILE,     g_kl, b, kvh, row0);
            cp_kv(pst + 2 * ATILE, g_v,  b, kvh, row0);
            asm volatile("cp.async.commit_group;" ::: "memory");
        }
    }

    float il0 = 1.0f / lrow0, il1 = 1.0f / lrow1;
    size_t b0 = (((size_t)(b * S_LEN + qg0)) * NH + h) * HD + tig * 2;
    size_t b1 = (((size_t)(b * S_LEN + qg1)) * NH + h) * HD + tig * 2;
    #pragma unroll
    for (int d = 0; d < 16; ++d) {
        *(uint32_t*)(g_ao + b0 + d * 8) = pack_h(oacc[d][0] * il0, oacc[d][1] * il0);
        *(uint32_t*)(g_ao + b1 + d * 8) = pack_h(oacc[d][2] * il1, oacc[d][3] * il1);
    }
}

// ---------------- launch ----------------------------------------------------
extern "C" void kernel_launch(void* const* d_in, const int* in_sizes, int n_in,
                              void* d_out, int out_size) {
    const float* x      = (const float*)d_in[0];
    const float* freqs  = (const float*)d_in[2];
    const int*   labels = (const int*)d_in[4];
    const float* wq     = (const float*)d_in[5];
    const float* wk     = (const float*)d_in[6];
    const float* wv     = (const float*)d_in[7];
    const float* wo     = (const float*)d_in[8];
    const float* ln1w   = (const float*)d_in[9];
    const float* ln1b   = (const float*)d_in[10];
    const float* ln2w   = (const float*)d_in[11];
    const float* ln2b   = (const float*)d_in[12];
    float* out = (float*)d_out;

    __half *xnh, *xnl, *ao;
    cudaGetSymbolAddress((void**)&xnh, g_xn_h);
    cudaGetSymbolAddress((void**)&xnl, g_xn_l);
    cudaGetSymbolAddress((void**)&ao,  g_ao);

    split_all<<<(TOT_F4 + 255) / 256, 256>>>(wq, wk, wv, wo);
    ln_kernel<<<ROWS, 256>>>(x, ln1w, ln1b, xnh, xnl);
    cumsum_kernel<<<2, 1024>>>(labels);

    size_t gemm_smem = 2 * STAGE_B;   // 81920 (restores L1 carveout)
    cudaFuncSetAttribute(qkv_gemm, cudaFuncAttributeMaxDynamicSharedMemorySize, (int)gemm_smem);
    cudaFuncSetAttribute(o_gemm, cudaFuncAttributeMaxDynamicSharedMemorySize, (int)gemm_smem);

    const float qscale = 0.08838834764831845f;   // 1/sqrt(128)
    qkv_gemm<<<dim3(24, ROWS / 128), 256, gemm_smem>>>(freqs, qscale);

    size_t attn_smem = 2 * QTILE + 2 * KVSTAGE;   // 174080
    cudaFuncSetAttribute(attn_kernel, cudaFuncAttributeMaxDynamicSharedMemorySize,
                         (int)attn_smem);
    attn_kernel<<<dim3(S_LEN / 128, NH, 2), 256, attn_smem>>>();

    ln_kernel_h<<<ROWS, 256>>>(ao, ln2w, ln2b, xnh, xnl);
    o_gemm<<<dim3(DIMN / 128, ROWS / 128), 256, gemm_smem>>>(out);
}

// round 14
// speedup vs baseline: 1.0514x; 1.0308x over previous
#include <cuda_runtime.h>
#include <cuda_fp16.h>
#include <math.h>
#include <stdint.h>

#define S_LEN 2048
#define DIMN  2048
#define NH    16
#define NKV   4
#define HD    128
#define ROWS  4096   // B*S

// ---------------- scratch (device globals; no allocation allowed) ----------
__device__ __half g_xn_h[ROWS * DIMN];
__device__ __half g_xn_l[ROWS * DIMN];
__device__ __half g_wq_h[DIMN * DIMN];
__device__ __half g_wq_l[DIMN * DIMN];
__device__ __half g_wk_h[512 * DIMN];
__device__ __half g_wk_l[512 * DIMN];
__device__ __half g_wv_h[512 * DIMN];    // single fp16 (2-term V proj)
__device__ __half g_wo_h[DIMN * DIMN];   // single fp16 (2-term o_gemm)
__device__ __half g_qh[ROWS * DIMN];  // roped+scaled Q hi/lo
__device__ __half g_ql[ROWS * DIMN];
__device__ __half g_kh[ROWS * 512];   // roped K hi/lo
__device__ __half g_kl[ROWS * 512];
__device__ __half g_v [ROWS * 512];   // V single fp16
__device__ __half g_ao[ROWS * DIMN];  // attention output, fp16
__device__ int   g_cs[2 * S_LEN];     // per-batch inclusive cumsum of labels

// ---------------- helpers ----------------------------------------------------
__device__ __forceinline__ uint32_t smem_to_u32(const void* p) {
    uint32_t a;
    asm("{ .reg .u64 t; cvta.to.shared.u64 t, %1; cvt.u32.u64 %0, t; }" : "=r"(a) : "l"(p));
    return a;
}
__device__ __forceinline__ void ldmx4(uint32_t* r, uint32_t addr) {
    asm volatile("ldmatrix.sync.aligned.m8n8.x4.shared.b16 {%0,%1,%2,%3}, [%4];"
        : "=r"(r[0]), "=r"(r[1]), "=r"(r[2]), "=r"(r[3]) : "r"(addr));
}
__device__ __forceinline__ void ldmx4t(uint32_t* r, uint32_t addr) {
    asm volatile("ldmatrix.sync.aligned.m8n8.x4.trans.shared.b16 {%0,%1,%2,%3}, [%4];"
        : "=r"(r[0]), "=r"(r[1]), "=r"(r[2]), "=r"(r[3]) : "r"(addr));
}
__device__ __forceinline__ void mma16816(float* c, const uint32_t* a, const uint32_t* b) {
    asm volatile(
        "mma.sync.aligned.m16n8k16.row.col.f32.f16.f16.f32 "
        "{%0,%1,%2,%3}, {%4,%5,%6,%7}, {%8,%9}, {%0,%1,%2,%3};"
        : "+f"(c[0]), "+f"(c[1]), "+f"(c[2]), "+f"(c[3])
        : "r"(a[0]), "r"(a[1]), "r"(a[2]), "r"(a[3]), "r"(b[0]), "r"(b[1]));
}
__device__ __forceinline__ void cp16(uint32_t d, const void* s) {
    asm volatile("cp.async.ca.shared.global [%0], [%1], 16;" :: "r"(d), "l"(s));
}
__device__ __forceinline__ void pack_hilo(float x, float y, uint32_t& h, uint32_t& l) {
    __half2 hb = __floats2half2_rn(x, y);
    float rx = x - __low2float(hb);
    float ry = y - __high2float(hb);
    __half2 lb = __floats2half2_rn(rx, ry);
    h = *(uint32_t*)&hb;
    l = *(uint32_t*)&lb;
}
__device__ __forceinline__ uint32_t pack_h(float x, float y) {
    __half2 hb = __floats2half2_rn(x, y);
    return *(uint32_t*)&hb;
}

// swizzled smem address: 64B rows of 4x16B chunks, chunk ^= (row>>1)&3
__device__ __forceinline__ uint32_t sw64(uint32_t base, int row, int chunk) {
    return base + row * 64 + ((chunk ^ ((row >> 1) & 3)) << 4);
}

// ---------------- cumsum of seizure labels (per batch) ---------------------
__global__ void cumsum_kernel(const int* __restrict__ labels) {
    __shared__ int bufA[S_LEN], bufB[S_LEN];
    int b = blockIdx.x;
    for (int i = threadIdx.x; i < S_LEN; i += blockDim.x)
        bufA[i] = labels[b * S_LEN + i];
    __syncthreads();
    int* src = bufA; int* dst = bufB;
    for (int off = 1; off < S_LEN; off <<= 1) {
        for (int i = threadIdx.x; i < S_LEN; i += blockDim.x)
            dst[i] = src[i] + (i >= off ? src[i - off] : 0);
        __syncthreads();
        int* t = src; src = dst; dst = t;
    }
    for (int i = threadIdx.x; i < S_LEN; i += blockDim.x)
        g_cs[b * S_LEN + i] = src[i];
}

// ---------------- merged weight split (all 4 weights in one launch) ---------
#define WQ_F4 1048576   // 2048*2048/4
#define WK_F4 262144    // 512*2048/4
#define WV_F4 262144
#define WO_F4 1048576
#define TOT_F4 (WQ_F4 + WK_F4 + WV_F4 + WO_F4)

__global__ void split_all(const float* __restrict__ wq, const float* __restrict__ wk,
                          const float* __restrict__ wv, const float* __restrict__ wo) {
    int i = blockIdx.x * blockDim.x + threadIdx.x;
    if (i >= TOT_F4) return;
    const float* src; __half *hi, *lo; int j = i;
    if (j < WQ_F4) { src = wq; hi = g_wq_h; lo = g_wq_l; }
    else if ((j -= WQ_F4) < WK_F4) { src = wk; hi = g_wk_h; lo = g_wk_l; }
    else if ((j -= WK_F4) < WV_F4) { src = wv; hi = g_wv_h; lo = nullptr; }
    else { j -= WV_F4; src = wo; hi = g_wo_h; lo = nullptr; }
    float4 v = ((const float4*)src)[j];
    uint32_t h01, h23, l01, l23;
    pack_hilo(v.x, v.y, h01, l01);
    pack_hilo(v.z, v.w, h23, l23);
    *(uint2*)(hi + (size_t)j * 4) = make_uint2(h01, h23);
    if (lo) *(uint2*)(lo + (size_t)j * 4) = make_uint2(l01, l23);
}

// ---------------- layernorm (fp32 in) -> fp16 hi/lo --------------------------
__global__ void ln_kernel(const float* __restrict__ in, const float* __restrict__ w,
                          const float* __restrict__ bvec,
                          __half* __restrict__ oh, __half* __restrict__ ol) {
    int row = blockIdx.x;
    const float* x = in + (size_t)row * DIMN;
    int tid = threadIdx.x;

    float4 v0 = *(const float4*)(x + tid * 4);
    float4 v1 = *(const float4*)(x + 1024 + tid * 4);
    float s  = v0.x + v0.y + v0.z + v0.w + v1.x + v1.y + v1.z + v1.w;
    float ss = v0.x*v0.x + v0.y*v0.y + v0.z*v0.z + v0.w*v0.w
             + v1.x*v1.x + v1.y*v1.y + v1.z*v1.z + v1.w*v1.w;
    #pragma unroll
    for (int off = 16; off; off >>= 1) {
        s  += __shfl_xor_sync(0xffffffffu, s,  off);
        ss += __shfl_xor_sync(0xffffffffu, ss, off);
    }
    __shared__ float rs[8], rss[8];
    __shared__ float s_mu, s_rstd;
    int wid = tid >> 5, lane = tid & 31;
    if (!lane) { rs[wid] = s; rss[wid] = ss; }
    __syncthreads();
    if (tid == 0) {
        float S = 0.f, SS = 0.f;
        #pragma unroll
        for (int i = 0; i < 8; ++i) { S += rs[i]; SS += rss[i]; }
        float mu = S / DIMN;
        s_mu = mu;
        s_rstd = rsqrtf(SS / DIMN - mu * mu + 1e-5f);
    }
    __syncthreads();
    float mu = s_mu, rstd = s_rstd;

    size_t base = (size_t)row * DIMN;
    #pragma unroll
    for (int half = 0; half < 2; ++half) {
        int off = half * 1024 + tid * 4;
        float4 v = half ? v1 : v0;
        float4 w4 = *(const float4*)(w + off);
        float4 b4 = *(const float4*)(bvec + off);
        float4 r;
        r.x = (v.x - mu) * rstd * w4.x + b4.x;
        r.y = (v.y - mu) * rstd * w4.y + b4.y;
        r.z = (v.z - mu) * rstd * w4.z + b4.z;
        r.w = (v.w - mu) * rstd * w4.w + b4.w;
        uint32_t h01, h23, l01, l23;
        pack_hilo(r.x, r.y, h01, l01);
        pack_hilo(r.z, r.w, h23, l23);
        *(uint2*)(oh + base + off) = make_uint2(h01, h23);
        *(uint2*)(ol + base + off) = make_uint2(l01, l23);
    }
}

// ---------------- layernorm (fp16 in) -> fp16 hi/lo --------------------------
__global__ void ln_kernel_h(const __half* __restrict__ in, const float* __restrict__ w,
                            const float* __restrict__ bvec,
                            __half* __restrict__ oh, __half* __restrict__ ol) {
    int row = blockIdx.x;
    const __half* x = in + (size_t)row * DIMN;
    int tid = threadIdx.x;

    uint4 u = *(const uint4*)(x + tid * 8);
    __half2 hv[4] = {*(__half2*)&u.x, *(__half2*)&u.y, *(__half2*)&u.z, *(__half2*)&u.w};
    float e[8];
    #pragma unroll
    for (int i = 0; i < 4; ++i) {
        float2 f = __half22float2(hv[i]);
        e[2 * i] = f.x; e[2 * i + 1] = f.y;
    }
    float s = 0.f, ss = 0.f;
    #pragma unroll
    for (int i = 0; i < 8; ++i) { s += e[i]; ss += e[i] * e[i]; }
    #pragma unroll
    for (int off = 16; off; off >>= 1) {
        s  += __shfl_xor_sync(0xffffffffu, s,  off);
        ss += __shfl_xor_sync(0xffffffffu, ss, off);
    }
    __shared__ float rs[8], rss[8];
    __shared__ float s_mu, s_rstd;
    int wid = tid >> 5, lane = tid & 31;
    if (!lane) { rs[wid] = s; rss[wid] = ss; }
    __syncthreads();
    if (tid == 0) {
        float S = 0.f, SS = 0.f;
        #pragma unroll
        for (int i = 0; i < 8; ++i) { S += rs[i]; SS += rss[i]; }
        float mu = S / DIMN;
        s_mu = mu;
        s_rstd = rsqrtf(SS / DIMN - mu * mu + 1e-5f);
    }
    __syncthreads();
    float mu = s_mu, rstd = s_rstd;

    size_t base = (size_t)row * DIMN + tid * 8;
    uint32_t hw[4], lw[4];
    #pragma unroll
    for (int i = 0; i < 4; ++i) {
        int off = tid * 8 + 2 * i;
        float2 w2 = *(const float2*)(w + off);
        float2 b2 = *(const float2*)(bvec + off);
        float rx = (e[2 * i]     - mu) * rstd * w2.x + b2.x;
        float ry = (e[2 * i + 1] - mu) * rstd * w2.y + b2.y;
        pack_hilo(rx, ry, hw[i], lw[i]);
    }
    *(uint4*)(oh + base) = make_uint4(hw[0], hw[1], hw[2], hw[3]);
    *(uint4*)(ol + base) = make_uint4(lw[0], lw[1], lw[2], lw[3]);
}

// ---------------- shared GEMM mainloops (swizzled 64B rows) ------------------
#define TILE_B (128 * 64)        // 8192 bytes per operand tile
#define STAGE_B (4 * TILE_B)     // 32768 bytes per stage (3-term layout)

__device__ __forceinline__ void cp_tile(uint32_t sdst, const __half* __restrict__ g,
                                        int row0, int K, int k0) {
    int tid = threadIdx.x;
    const char* gb = (const char*)(g + (size_t)row0 * K + k0);
    size_t rb = (size_t)K * 2;
    #pragma unroll
    for (int j = 0; j < 2; ++j) {
        int lin = j * 256 + tid;
        int r = lin >> 2, c = lin & 3;
        cp16(sw64(sdst, r, c), gb + (size_t)r * rb + c * 16);
    }
}

// 3-term mainloop (2 stages): D += Ah Bh + Ah Bl + Al Bh
__device__ __forceinline__ void gemm_mainloop(
        const __half* __restrict__ Ah, const __half* __restrict__ Al,
        const __half* __restrict__ Bh, const __half* __restrict__ Bl,
        int row0, int col0, int K, uint32_t sb, float acc[4][4][4]) {
    int tid = threadIdx.x, lane = tid & 31, wid = tid >> 5;
    int wm = wid & 1, wn = wid >> 1;

    const int nst = K >> 5;
    cp_tile(sb,              Ah, row0, K, 0);
    cp_tile(sb + TILE_B,     Al, row0, K, 0);
    cp_tile(sb + 2 * TILE_B, Bh, col0, K, 0);
    cp_tile(sb + 3 * TILE_B, Bl, col0, K, 0);
    asm volatile("cp.async.commit_group;" ::: "memory");

    const int arow = wm * 64 + (lane & 15);
    const int ac   = lane >> 4;
    const int brow = wn * 32 + (lane & 7);
    const int bc   = ((lane >> 3) & 1) | ((lane >> 4) << 1);

    for (int i = 0; i < nst; ++i) {
        asm volatile("cp.async.wait_group 0;" ::: "memory");
        __syncthreads();

        if (i + 1 < nst) {
            uint32_t pst = sb + ((i + 1) & 1) * STAGE_B;
            int k0 = (i + 1) << 5;
            cp_tile(pst,              Ah, row0, K, k0);
            cp_tile(pst + TILE_B,     Al, row0, K, k0);
            cp_tile(pst + 2 * TILE_B, Bh, col0, K, k0);
            cp_tile(pst + 3 * TILE_B, Bl, col0, K, k0);
            asm volatile("cp.async.commit_group;" ::: "memory");
        }

        uint32_t st = sb + (i & 1) * STAGE_B;
        uint32_t bh[4][4], bl[4][4];
        #pragma unroll
        for (int ni = 0; ni < 4; ++ni) {
            ldmx4(bh[ni], sw64(st + 2 * TILE_B, brow + ni * 8, bc));
            ldmx4(bl[ni], sw64(st + 3 * TILE_B, brow + ni * 8, bc));
        }

        #pragma unroll
        for (int mi = 0; mi < 4; ++mi) {
            int row = arow + mi * 16;
            uint32_t ah0[4], al0[4], ah1[4], al1[4];
            ldmx4(ah0, sw64(st,          row, ac));
            ldmx4(al0, sw64(st + TILE_B, row, ac));
            ldmx4(ah1, sw64(st,          row, ac + 2));
            ldmx4(al1, sw64(st + TILE_B, row, ac + 2));
            #pragma unroll
            for (int ni = 0; ni < 4; ++ni) {
                mma16816(acc[mi][ni], ah0, bh[ni]);
                mma16816(acc[mi][ni], ah0, bl[ni]);
                mma16816(acc[mi][ni], al0, bh[ni]);
            }
            #pragma unroll
            for (int ni = 0; ni < 4; ++ni) {
                mma16816(acc[mi][ni], ah1, bh[ni] + 2);
                mma16816(acc[mi][ni], ah1, bl[ni] + 2);
                mma16816(acc[mi][ni], al1, bh[ni] + 2);
            }
        }
    }
    __syncthreads();
}

// 2-term mainloop (2 stages): D += Ah Bh + Al Bh  (B single fp16)
__device__ __forceinline__ void gemm_mainloop2(
        const __half* __restrict__ Ah, const __half* __restrict__ Al,
        const __half* __restrict__ Bh,
        int row0, int col0, int K, uint32_t sb, float acc[4][4][4]) {
    int tid = threadIdx.x, lane = tid & 31, wid = tid >> 5;
    int wm = wid & 1, wn = wid >> 1;

    const int nst = K >> 5;
    cp_tile(sb,              Ah, row0, K, 0);
    cp_tile(sb + TILE_B,     Al, row0, K, 0);
    cp_tile(sb + 2 * TILE_B, Bh, col0, K, 0);
    asm volatile("cp.async.commit_group;" ::: "memory");

    const int arow = wm * 64 + (lane & 15);
    const int ac   = lane >> 4;
    const int brow = wn * 32 + (lane & 7);
    const int bc   = ((lane >> 3) & 1) | ((lane >> 4) << 1);

    for (int i = 0; i < nst; ++i) {
        asm volatile("cp.async.wait_group 0;" ::: "memory");
        __syncthreads();

        if (i + 1 < nst) {
            uint32_t pst = sb + ((i + 1) & 1) * STAGE_B;
            int k0 = (i + 1) << 5;
            cp_tile(pst,              Ah, row0, K, k0);
            cp_tile(pst + TILE_B,     Al, row0, K, k0);
            cp_tile(pst + 2 * TILE_B, Bh, col0, K, k0);
            asm volatile("cp.async.commit_group;" ::: "memory");
        }

        uint32_t st = sb + (i & 1) * STAGE_B;
        uint32_t bh[4][4];
        #pragma unroll
        for (int ni = 0; ni < 4; ++ni)
            ldmx4(bh[ni], sw64(st + 2 * TILE_B, brow + ni * 8, bc));

        #pragma unroll
        for (int mi = 0; mi < 4; ++mi) {
            int row = arow + mi * 16;
            uint32_t ah0[4], al0[4], ah1[4], al1[4];
            ldmx4(ah0, sw64(st,          row, ac));
            ldmx4(al0, sw64(st + TILE_B, row, ac));
            ldmx4(ah1, sw64(st,          row, ac + 2));
            ldmx4(al1, sw64(st + TILE_B, row, ac + 2));
            #pragma unroll
            for (int ni = 0; ni < 4; ++ni) {
                mma16816(acc[mi][ni], ah0, bh[ni]);
                mma16816(acc[mi][ni], al0, bh[ni]);
            }
            #pragma unroll
            for (int ni = 0; ni < 4; ++ni) {
                mma16816(acc[mi][ni], ah1, bh[ni] + 2);
                mma16816(acc[mi][ni], al1, bh[ni] + 2);
            }
        }
    }
    __syncthreads();
}

// ---------------- merged QKV projection (one launch) ------------------------
// blockIdx.x: [0,16) -> Q (rope+scale, 3-term), [16,20) -> K (rope, 3-term),
//             [20,24) -> V (2-term, single fp16 out)
__global__ __launch_bounds__(256, 2)
void qkv_gemm(const float* __restrict__ fr, float qscale) {
    extern __shared__ char sm[];
    uint32_t sb = smem_to_u32(sm);
    int bx = blockIdx.x;
    int tid = threadIdx.x, lane = tid & 31, wid = tid >> 5;
    int wm = wid & 1, wn = wid >> 1;
    int row0 = blockIdx.y * 128;

    float acc[4][4][4];
    #pragma unroll
    for (int i = 0; i < 4; ++i)
        #pragma unroll
        for (int j = 0; j < 4; ++j)
            #pragma unroll
            for (int q = 0; q < 4; ++q) acc[i][j][q] = 0.f;

    __half *Oh, *Ol;
    int N, col0, do_rope;
    float scale;
    if (bx < 16) {
        Oh = g_qh; Ol = g_ql;
        N = DIMN; col0 = bx * 128; do_rope = 1; scale = qscale;
        gemm_mainloop(g_xn_h, g_xn_l, g_wq_h, g_wq_l, row0, col0, DIMN, sb, acc);
    } else if (bx < 20) {
        Oh = g_kh; Ol = g_kl;
        N = 512; col0 = (bx - 16) * 128; do_rope = 1; scale = 1.0f;
        gemm_mainloop(g_xn_h, g_xn_l, g_wk_h, g_wk_l, row0, col0, DIMN, sb, acc);
    } else {
        Oh = g_v; Ol = nullptr;
        N = 512; col0 = (bx - 20) * 128; do_rope = 0; scale = 1.0f;
        gemm_mainloop2(g_xn_h, g_xn_l, g_wv_h, row0, col0, DIMN, sb, acc);
    }

    int mrow = row0 + wm * 64 + (lane >> 2);
    int ncol = col0 + wn * 32 + (lane & 3) * 2;
    #pragma unroll
    for (int mi = 0; mi < 4; ++mi)
        #pragma unroll
        for (int ni = 0; ni < 4; ++ni) {
            int col = ncol + ni * 8;
            int r0 = mrow + mi * 16, r1 = r0 + 8;
            float x0 = acc[mi][ni][0], y0 = acc[mi][ni][1];
            float x1 = acc[mi][ni][2], y1 = acc[mi][ni][3];
            if (do_rope) {
                int fi = (col & 127) >> 1;
                int s0 = r0 & (S_LEN - 1), s1 = r1 & (S_LEN - 1);
                float c0 = fr[(s0 * 64 + fi) * 2], n0 = fr[(s0 * 64 + fi) * 2 + 1];
                float c1 = fr[(s1 * 64 + fi) * 2], n1 = fr[(s1 * 64 + fi) * 2 + 1];
                float tx0 = (x0 * c0 - y0 * n0) * scale;
                float ty0 = (x0 * n0 + y0 * c0) * scale;
                float tx1 = (x1 * c1 - y1 * n1) * scale;
                float ty1 = (x1 * n1 + y1 * c1) * scale;
                x0 = tx0; y0 = ty0; x1 = tx1; y1 = ty1;
            }
            uint32_t h0, l0, h1, l1;
            pack_hilo(x0, y0, h0, l0);
            pack_hilo(x1, y1, h1, l1);
            *(uint32_t*)(Oh + (size_t)r0 * N + col) = h0;
            *(uint32_t*)(Oh + (size_t)r1 * N + col) = h1;
            if (Ol) {
                *(uint32_t*)(Ol + (size_t)r0 * N + col) = l0;
                *(uint32_t*)(Ol + (size_t)r1 * N + col) = l1;
            }
        }
}

// ---------------- output projection: out = xn * wo^T (2-term fp16) ----------
__global__ __launch_bounds__(256, 2)
void o_gemm(float* __restrict__ C) {
    extern __shared__ char sm[];
    uint32_t sb = smem_to_u32(sm);
    int tid = threadIdx.x, lane = tid & 31, wid = tid >> 5;
    int wm = wid & 1, wn = wid >> 1;
    int row0 = blockIdx.y * 128, col0 = blockIdx.x * 128;

    float acc[4][4][4];
    #pragma unroll
    for (int i = 0; i < 4; ++i)
        #pragma unroll
        for (int j = 0; j < 4; ++j)
            #pragma unroll
            for (int q = 0; q < 4; ++q) acc[i][j][q] = 0.f;

    gemm_mainloop2(g_xn_h, g_xn_l, g_wo_h, row0, col0, DIMN, sb, acc);

    int mrow = row0 + wm * 64 + (lane >> 2);
    int ncol = col0 + wn * 32 + (lane & 3) * 2;
    #pragma unroll
    for (int mi = 0; mi < 4; ++mi)
        #pragma unroll
        for (int ni = 0; ni < 4; ++ni) {
            float* p0 = C + (size_t)(mrow + mi * 16) * DIMN + ncol + ni * 8;
            float* p1 = C + (size_t)(mrow + mi * 16 + 8) * DIMN + ncol + ni * 8;
            *(float2*)p0 = make_float2(acc[mi][ni][0], acc[mi][ni][1]);
            *(float2*)p1 = make_float2(acc[mi][ni][2], acc[mi][ni][3]);
        }
}

// ---------------- tensor-core flash attention --------------------------------
// QK 3-term (K frags via x4 covering k32); PV 1-term. Stage: Kh,Kl,V.
#define APITCH 272
#define ATILE  (64 * APITCH)     // 17408 bytes
#define QTILE  (128 * APITCH)    // 34816 bytes
#define KVSTAGE (3 * ATILE)

__device__ __forceinline__ void cp_kv(uint32_t dst, const __half* __restrict__ g,
                                      int b, int kvh, int row0) {
    int tid = threadIdx.x;
    #pragma unroll
    for (int j = 0; j < 4; ++j) {
        int lin = j * 256 + tid;
        int r = lin >> 4, c = lin & 15;
        const __half* s = g + (((size_t)(b * S_LEN + row0 + r)) * NKV + kvh) * HD + c * 8;
        cp16(dst + r * APITCH + c * 16, s);
    }
}

__global__ __launch_bounds__(256, 1)
void attn_kernel() {
    extern __shared__ char asm_[];
    uint32_t sb = smem_to_u32(asm_);
    const uint32_t smQh = sb;
    const uint32_t smQl = sb + QTILE;
    const uint32_t smKV = sb + 2 * QTILE;

    const int tid = threadIdx.x;
    const int lane = tid & 31, wid = tid >> 5;
    const int gid = lane >> 2, tig = lane & 3;
    const int qt = (int)gridDim.x - 1 - (int)blockIdx.x;   // largest-first
    const int q0 = qt * 128;
    const int h  = blockIdx.y;
    const int b  = blockIdx.z;
    const int kvh = h >> 2;
    const int m0 = wid * 16;
    const int nkt = 2 * (qt + 1);

    #pragma unroll
    for (int j = 0; j < 8; ++j) {
        int lin = j * 256 + tid;
        int r = lin >> 4, c = lin & 15;
        size_t go = (((size_t)(b * S_LEN + q0 + r)) * NH + h) * HD + c * 8;
        cp16(smQh + r * APITCH + c * 16, g_qh + go);
        cp16(smQl + r * APITCH + c * 16, g_ql + go);
    }
    cp_kv(smKV,             g_kh, b, kvh, 0);
    cp_kv(smKV + ATILE,     g_kl, b, kvh, 0);
    cp_kv(smKV + 2 * ATILE, g_v,  b, kvh, 0);
    asm volatile("cp.async.commit_group;" ::: "memory");
    {
        uint32_t st = smKV + KVSTAGE;
        cp_kv(st,             g_kh, b, kvh, 64);
        cp_kv(st + ATILE,     g_kl, b, kvh, 64);
        cp_kv(st + 2 * ATILE, g_v,  b, kvh, 64);
        asm volatile("cp.async.commit_group;" ::: "memory");
    }

    const int qg0 = q0 + m0 + gid;
    const int qg1 = qg0 + 8;
    const int qmax = q0 + m0 + 15;
    const int csq0 = (qg0 > 0) ? g_cs[b * S_LEN + qg0 - 1] : 0;
    const int csq1 = g_cs[b * S_LEN + qg1 - 1];

    float oacc[16][4];
    #pragma unroll
    for (int d = 0; d < 16; ++d)
        #pragma unroll
        for (int q = 0; q < 4; ++q) oacc[d][q] = 0.f;
    float mrow0 = -1e30f, mrow1 = -1e30f, lrow0 = 0.f, lrow1 = 0.f;

    for (int it = 0; it < nkt; ++it) {
        const int k0 = it * 64;
        if (it + 1 < nkt) asm volatile("cp.async.wait_group 1;" ::: "memory");
        else              asm volatile("cp.async.wait_group 0;" ::: "memory");
        __syncthreads();

        if (k0 <= qmax) {
            const uint32_t st  = smKV + (it & 1) * KVSTAGE;
            const uint32_t sKh = st, sKl = st + ATILE, sV = st + 2 * ATILE;

            float sacc[8][4];
            #pragma unroll
            for (int j = 0; j < 8; ++j)
                #pragma unroll
                for (int q = 0; q < 4; ++q) sacc[j][q] = 0.f;

            const uint32_t qoff = (m0 + (lane & 15)) * APITCH + (lane >> 4) * 16;
            const uint32_t koff = (lane & 7) * APITCH + (lane >> 3) * 16;  // x4: k32
            #pragma unroll
            for (int kk2 = 0; kk2 < 4; ++kk2) {
                uint32_t qh0[4], ql0[4], qh1[4], ql1[4];
                uint32_t qa = qoff + kk2 * 64;
                ldmx4(qh0, smQh + qa);
                ldmx4(ql0, smQl + qa);
                ldmx4(qh1, smQh + qa + 32);
                ldmx4(ql1, smQl + qa + 32);
                #pragma unroll
                for (int j = 0; j < 8; ++j) {
                    uint32_t kh[4], kl[4];
                    uint32_t ka = koff + j * 8 * APITCH + kk2 * 64;
                    ldmx4(kh, sKh + ka);
                    ldmx4(kl, sKl + ka);
                    mma16816(sacc[j], qh0, kh);
                    mma16816(sacc[j], qh0, kl);
                    mma16816(sacc[j], ql0, kh);
                    mma16816(sacc[j], qh1, kh + 2);
                    mma16816(sacc[j], qh1, kl + 2);
                    mma16816(sacc[j], ql1, kh + 2);
                }
            }

            if (k0 + 73 >= q0 + m0) {
                #pragma unroll
                for (int j = 0; j < 8; ++j) {
                    int kg0 = k0 + j * 8 + tig * 2;
                    int kg1 = kg0 + 1;
                    int bi0 = kg0 + 10; if (bi0 > S_LEN - 1) bi0 = S_LEN - 1;
                    int bi1 = kg1 + 10; if (bi1 > S_LEN - 1) bi1 = S_LEN - 1;
                    int ck0 = g_cs[b * S_LEN + bi0];
                    int ck1 = g_cs[b * S_LEN + bi1];
                    if (kg0 + 10 >= qg0 && ck0 - csq0 > 0) sacc[j][0] += 2.0f;
                    if (kg1 + 10 >= qg0 && ck1 - csq0 > 0) sacc[j][1] += 2.0f;
                    if (kg0 + 10 >= qg1 && ck0 - csq1 > 0) sacc[j][2] += 2.0f;
                    if (kg1 + 10 >= qg1 && ck1 - csq1 > 0) sacc[j][3] += 2.0f;
                }
            }
            if (k0 + 63 > qg0) {
                #pragma unroll
                for (int j = 0; j < 8; ++j) {
                    int kg0 = k0 + j * 8 + tig * 2;
                    int kg1 = kg0 + 1;
                    if (kg0 > qg0) sacc[j][0] = -1e9f;
                    if (kg1 > qg0) sacc[j][1] = -1e9f;
                    if (kg0 > qg1) sacc[j][2] = -1e9f;
                    if (kg1 > qg1) sacc[j][3] = -1e9f;
                }
            }

            float mx0 = -1e30f, mx1 = -1e30f;
            #pragma unroll
            for (int j = 0; j < 8; ++j) {
                mx0 = fmaxf(mx0, fmaxf(sacc[j][0], sacc[j][1]));
                mx1 = fmaxf(mx1, fmaxf(sacc[j][2], sacc[j][3]));
            }
            mx0 = fmaxf(mx0, __shfl_xor_sync(0xffffffffu, mx0, 1));
            mx0 = fmaxf(mx0, __shfl_xor_sync(0xffffffffu, mx0, 2));
            mx1 = fmaxf(mx1, __shfl_xor_sync(0xffffffffu, mx1, 1));
            mx1 = fmaxf(mx1, __shfl_xor_sync(0xffffffffu, mx1, 2));
            float mn0 = fmaxf(mrow0, mx0), mn1 = fmaxf(mrow1, mx1);
            float a0 = __expf(mrow0 - mn0), a1 = __expf(mrow1 - mn1);
            mrow0 = mn0; mrow1 = mn1;
            float sum0 = 0.f, sum1 = 0.f;
            #pragma unroll
            for (int j = 0; j < 8; ++j) {
                sacc[j][0] = __expf(sacc[j][0] - mn0); sum0 += sacc[j][0];
                sacc[j][1] = __expf(sacc[j][1] - mn0); sum0 += sacc[j][1];
                sacc[j][2] = __expf(sacc[j][2] - mn1); sum1 += sacc[j][2];
                sacc[j][3] = __expf(sacc[j][3] - mn1); sum1 += sacc[j][3];
            }
            sum0 += __shfl_xor_sync(0xffffffffu, sum0, 1);
            sum0 += __shfl_xor_sync(0xffffffffu, sum0, 2);
            sum1 += __shfl_xor_sync(0xffffffffu, sum1, 1);
            sum1 += __shfl_xor_sync(0xffffffffu, sum1, 2);
            lrow0 = lrow0 * a0 + sum0;
            lrow1 = lrow1 * a1 + sum1;
            #pragma unroll
            for (int d = 0; d < 16; ++d) {
                oacc[d][0] *= a0; oacc[d][1] *= a0;
                oacc[d][2] *= a1; oacc[d][3] *= a1;
            }

            uint32_t ph[4][4];
            #pragma unroll
            for (int t = 0; t < 4; ++t) {
                int j0 = 2 * t, j1 = 2 * t + 1;
                ph[t][0] = pack_h(sacc[j0][0], sacc[j0][1]);
                ph[t][1] = pack_h(sacc[j0][2], sacc[j0][3]);
                ph[t][2] = pack_h(sacc[j1][0], sacc[j1][1]);
                ph[t][3] = pack_h(sacc[j1][2], sacc[j1][3]);
            }

            const uint32_t voff = (lane & 15) * APITCH + (lane >> 4) * 16;
            #pragma unroll
            for (int t = 0; t < 4; ++t) {
                #pragma unroll
                for (int dn2 = 0; dn2 < 8; ++dn2) {
                    uint32_t vh[4];
                    ldmx4t(vh, sV + voff + t * 16 * APITCH + dn2 * 32);
                    mma16816(oacc[2 * dn2],     ph[t], vh);
                    mma16816(oacc[2 * dn2 + 1], ph[t], vh + 2);
                }
            }
        }
        __syncthreads();

        if (it + 2 < nkt) {
            uint32_t pst = smKV + (it & 1) * KVSTAGE;
            int row0 = (it + 2) * 64;
            cp_kv(pst,             g_kh, b, kvh, row0);
            cp_kv(pst + ATILE,     g_kl, b, kvh, row0);
            cp_kv(pst + 2 * ATILE, g_v,  b, kvh, row0);
            asm volatile("cp.async.commit_group;" ::: "memory");
        }
    }

    float il0 = 1.0f / lrow0, il1 = 1.0f / lrow1;
    size_t b0 = (((size_t)(b * S_LEN + qg0)) * NH + h) * HD + tig * 2;
    size_t b1 = (((size_t)(b * S_LEN + qg1)) * NH + h) * HD + tig * 2;
    #pragma unroll
    for (int d = 0; d < 16; ++d) {
        *(uint32_t*)(g_ao + b0 + d * 8) = pack_h(oacc[d][0] * il0, oacc[d][1] * il0);
        *(uint32_t*)(g_ao + b1 + d * 8) = pack_h(oacc[d][2] * il1, oacc[d][3] * il1);
    }
}

// ---------------- launch ----------------------------------------------------
extern "C" void kernel_launch(void* const* d_in, const int* in_sizes, int n_in,
                              void* d_out, int out_size) {
    const float* x      = (const float*)d_in[0];
    const float* freqs  = (const float*)d_in[2];
    const int*   labels = (const int*)d_in[4];
    const float* wq     = (const float*)d_in[5];
    const float* wk     = (const float*)d_in[6];
    const float* wv     = (const float*)d_in[7];
    const float* wo     = (const float*)d_in[8];
    const float* ln1w   = (const float*)d_in[9];
    const float* ln1b   = (const float*)d_in[10];
    const float* ln2w   = (const float*)d_in[11];
    const float* ln2b   = (const float*)d_in[12];
    float* out = (float*)d_out;

    __half *xnh, *xnl, *ao;
    cudaGetSymbolAddress((void**)&xnh, g_xn_h);
    cudaGetSymbolAddress((void**)&xnl, g_xn_l);
    cudaGetSymbolAddress((void**)&ao,  g_ao);

    split_all<<<(TOT_F4 + 255) / 256, 256>>>(wq, wk, wv, wo);
    ln_kernel<<<ROWS, 256>>>(x, ln1w, ln1b, xnh, xnl);
    cumsum_kernel<<<2, 1024>>>(labels);

    size_t gemm_smem = 2 * STAGE_B;   // 65536 — L1 carveout grows to ~100KB
    cudaFuncSetAttribute(qkv_gemm, cudaFuncAttributeMaxDynamicSharedMemorySize, (int)gemm_smem);
    cudaFuncSetAttribute(o_gemm, cudaFuncAttributeMaxDynamicSharedMemorySize, (int)gemm_smem);

    const float qscale = 0.08838834764831845f;   // 1/sqrt(128)
    qkv_gemm<<<dim3(24, ROWS / 128), 256, gemm_smem>>>(freqs, qscale);

    size_t attn_smem = 2 * QTILE + 2 * KVSTAGE;   // 174080
    cudaFuncSetAttribute(attn_kernel, cudaFuncAttributeMaxDynamicSharedMemorySize,
                         (int)attn_smem);
    attn_kernel<<<dim3(S_LEN / 128, NH, 2), 256, attn_smem>>>();

    ln_kernel_h<<<ROWS, 256>>>(ao, ln2w, ln2b, xnh, xnl);
    o_gemm<<<dim3(DIMN / 128, ROWS / 128), 256, gemm_smem>>>(out);
}

// round 15
// speedup vs baseline: 1.0533x; 1.0018x over previous
#include <cuda_runtime.h>
#include <cuda_fp16.h>
#include <math.h>
#include <stdint.h>

#define S_LEN 2048
#define DIMN  2048
#define NH    16
#define NKV   4
#define HD    128
#define ROWS  4096   // B*S

// ---------------- scratch (device globals; no allocation allowed) ----------
__device__ __half g_xn_h[ROWS * DIMN];
__device__ __half g_xn_l[ROWS * DIMN];
__device__ __half g_wq_h[DIMN * DIMN];
__device__ __half g_wq_l[DIMN * DIMN];
__device__ __half g_wk_h[512 * DIMN];
__device__ __half g_wk_l[512 * DIMN];
__device__ __half g_wv_h[512 * DIMN];    // single fp16 (2-term V proj)
__device__ __half g_wo_h[DIMN * DIMN];   // single fp16 (2-term o_gemm)
__device__ __half g_qh[ROWS * DIMN];  // roped+scaled Q hi/lo
__device__ __half g_ql[ROWS * DIMN];
__device__ __half g_kh[ROWS * 512];   // roped K hi/lo
__device__ __half g_kl[ROWS * 512];
__device__ __half g_v [ROWS * 512];   // V single fp16
__device__ __half g_ao[ROWS * DIMN];  // attention output, fp16
__device__ int   g_cs[2 * S_LEN];     // per-batch inclusive cumsum of labels

// ---------------- helpers ----------------------------------------------------
__device__ __forceinline__ uint32_t smem_to_u32(const void* p) {
    uint32_t a;
    asm("{ .reg .u64 t; cvta.to.shared.u64 t, %1; cvt.u32.u64 %0, t; }" : "=r"(a) : "l"(p));
    return a;
}
__device__ __forceinline__ void ldmx4(uint32_t* r, uint32_t addr) {
    asm volatile("ldmatrix.sync.aligned.m8n8.x4.shared.b16 {%0,%1,%2,%3}, [%4];"
        : "=r"(r[0]), "=r"(r[1]), "=r"(r[2]), "=r"(r[3]) : "r"(addr));
}
__device__ __forceinline__ void ldmx4t(uint32_t* r, uint32_t addr) {
    asm volatile("ldmatrix.sync.aligned.m8n8.x4.trans.shared.b16 {%0,%1,%2,%3}, [%4];"
        : "=r"(r[0]), "=r"(r[1]), "=r"(r[2]), "=r"(r[3]) : "r"(addr));
}
__device__ __forceinline__ void mma16816(float* c, const uint32_t* a, const uint32_t* b) {
    asm volatile(
        "mma.sync.aligned.m16n8k16.row.col.f32.f16.f16.f32 "
        "{%0,%1,%2,%3}, {%4,%5,%6,%7}, {%8,%9}, {%0,%1,%2,%3};"
        : "+f"(c[0]), "+f"(c[1]), "+f"(c[2]), "+f"(c[3])
        : "r"(a[0]), "r"(a[1]), "r"(a[2]), "r"(a[3]), "r"(b[0]), "r"(b[1]));
}
__device__ __forceinline__ void cp16(uint32_t d, const void* s) {
    asm volatile("cp.async.ca.shared.global [%0], [%1], 16;" :: "r"(d), "l"(s));
}
__device__ __forceinline__ void pack_hilo(float x, float y, uint32_t& h, uint32_t& l) {
    __half2 hb = __floats2half2_rn(x, y);
    float rx = x - __low2float(hb);
    float ry = y - __high2float(hb);
    __half2 lb = __floats2half2_rn(rx, ry);
    h = *(uint32_t*)&hb;
    l = *(uint32_t*)&lb;
}
__device__ __forceinline__ uint32_t pack_h(float x, float y) {
    __half2 hb = __floats2half2_rn(x, y);
    return *(uint32_t*)&hb;
}

// swizzled smem address: 64B rows of 4x16B chunks, chunk ^= (row>>1)&3
__device__ __forceinline__ uint32_t sw64(uint32_t base, int row, int chunk) {
    return base + row * 64 + ((chunk ^ ((row >> 1) & 3)) << 4);
}

// ---------------- cumsum of seizure labels (per batch) ---------------------
__global__ void cumsum_kernel(const int* __restrict__ labels) {
    __shared__ int bufA[S_LEN], bufB[S_LEN];
    int b = blockIdx.x;
    for (int i = threadIdx.x; i < S_LEN; i += blockDim.x)
        bufA[i] = labels[b * S_LEN + i];
    __syncthreads();
    int* src = bufA; int* dst = bufB;
    for (int off = 1; off < S_LEN; off <<= 1) {
        for (int i = threadIdx.x; i < S_LEN; i += blockDim.x)
            dst[i] = src[i] + (i >= off ? src[i - off] : 0);
        __syncthreads();
        int* t = src; src = dst; dst = t;
    }
    for (int i = threadIdx.x; i < S_LEN; i += blockDim.x)
        g_cs[b * S_LEN + i] = src[i];
}

// ---------------- merged weight split: 4 float4 per thread (MLP=4) ----------
#define WQ_F4 1048576   // 2048*2048/4
#define WK_F4 262144    // 512*2048/4
#define WV_F4 262144
#define WO_F4 1048576
#define TOT_F4 (WQ_F4 + WK_F4 + WV_F4 + WO_F4)
// block covers 1024 f4; weight boundaries are multiples of 262144 -> never straddled

__global__ void split_all(const float* __restrict__ wq, const float* __restrict__ wk,
                          const float* __restrict__ wv, const float* __restrict__ wo) {
    int blk0 = blockIdx.x * 1024;
    const float* src; __half *hi, *lo; int base;
    if (blk0 < WQ_F4) { src = wq; hi = g_wq_h; lo = g_wq_l; base = 0; }
    else if (blk0 < WQ_F4 + WK_F4) { src = wk; hi = g_wk_h; lo = g_wk_l; base = WQ_F4; }
    else if (blk0 < WQ_F4 + WK_F4 + WV_F4) { src = wv; hi = g_wv_h; lo = nullptr; base = WQ_F4 + WK_F4; }
    else { src = wo; hi = g_wo_h; lo = nullptr; base = WQ_F4 + WK_F4 + WV_F4; }
    int j0 = blk0 - base + threadIdx.x;

    float4 v[4];
    #pragma unroll
    for (int t = 0; t < 4; ++t)
        v[t] = ((const float4*)src)[j0 + t * 256];
    #pragma unroll
    for (int t = 0; t < 4; ++t) {
        int j = j0 + t * 256;
        uint32_t h01, h23, l01, l23;
        pack_hilo(v[t].x, v[t].y, h01, l01);
        pack_hilo(v[t].z, v[t].w, h23, l23);
        *(uint2*)(hi + (size_t)j * 4) = make_uint2(h01, h23);
        if (lo) *(uint2*)(lo + (size_t)j * 4) = make_uint2(l01, l23);
    }
}

// ---------------- layernorm (fp32 in) -> fp16 hi/lo --------------------------
__global__ void ln_kernel(const float* __restrict__ in, const float* __restrict__ w,
                          const float* __restrict__ bvec,
                          __half* __restrict__ oh, __half* __restrict__ ol) {
    int row = blockIdx.x;
    const float* x = in + (size_t)row * DIMN;
    int tid = threadIdx.x;

    float4 v0 = *(const float4*)(x + tid * 4);
    float4 v1 = *(const float4*)(x + 1024 + tid * 4);
    float s  = v0.x + v0.y + v0.z + v0.w + v1.x + v1.y + v1.z + v1.w;
    float ss = v0.x*v0.x + v0.y*v0.y + v0.z*v0.z + v0.w*v0.w
             + v1.x*v1.x + v1.y*v1.y + v1.z*v1.z + v1.w*v1.w;
    #pragma unroll
    for (int off = 16; off; off >>= 1) {
        s  += __shfl_xor_sync(0xffffffffu, s,  off);
        ss += __shfl_xor_sync(0xffffffffu, ss, off);
    }
    __shared__ float rs[8], rss[8];
    __shared__ float s_mu, s_rstd;
    int wid = tid >> 5, lane = tid & 31;
    if (!lane) { rs[wid] = s; rss[wid] = ss; }
    __syncthreads();
    if (tid == 0) {
        float S = 0.f, SS = 0.f;
        #pragma unroll
        for (int i = 0; i < 8; ++i) { S += rs[i]; SS += rss[i]; }
        float mu = S / DIMN;
        s_mu = mu;
        s_rstd = rsqrtf(SS / DIMN - mu * mu + 1e-5f);
    }
    __syncthreads();
    float mu = s_mu, rstd = s_rstd;

    size_t base = (size_t)row * DIMN;
    #pragma unroll
    for (int half = 0; half < 2; ++half) {
        int off = half * 1024 + tid * 4;
        float4 v = half ? v1 : v0;
        float4 w4 = *(const float4*)(w + off);
        float4 b4 = *(const float4*)(bvec + off);
        float4 r;
        r.x = (v.x - mu) * rstd * w4.x + b4.x;
        r.y = (v.y - mu) * rstd * w4.y + b4.y;
        r.z = (v.z - mu) * rstd * w4.z + b4.z;
        r.w = (v.w - mu) * rstd * w4.w + b4.w;
        uint32_t h01, h23, l01, l23;
        pack_hilo(r.x, r.y, h01, l01);
        pack_hilo(r.z, r.w, h23, l23);
        *(uint2*)(oh + base + off) = make_uint2(h01, h23);
        *(uint2*)(ol + base + off) = make_uint2(l01, l23);
    }
}

// ---------------- layernorm (fp16 in) -> fp16 hi/lo --------------------------
__global__ void ln_kernel_h(const __half* __restrict__ in, const float* __restrict__ w,
                            const float* __restrict__ bvec,
                            __half* __restrict__ oh, __half* __restrict__ ol) {
    int row = blockIdx.x;
    const __half* x = in + (size_t)row * DIMN;
    int tid = threadIdx.x;

    uint4 u = *(const uint4*)(x + tid * 8);
    __half2 hv[4] = {*(__half2*)&u.x, *(__half2*)&u.y, *(__half2*)&u.z, *(__half2*)&u.w};
    float e[8];
    #pragma unroll
    for (int i = 0; i < 4; ++i) {
        float2 f = __half22float2(hv[i]);
        e[2 * i] = f.x; e[2 * i + 1] = f.y;
    }
    float s = 0.f, ss = 0.f;
    #pragma unroll
    for (int i = 0; i < 8; ++i) { s += e[i]; ss += e[i] * e[i]; }
    #pragma unroll
    for (int off = 16; off; off >>= 1) {
        s  += __shfl_xor_sync(0xffffffffu, s,  off);
        ss += __shfl_xor_sync(0xffffffffu, ss, off);
    }
    __shared__ float rs[8], rss[8];
    __shared__ float s_mu, s_rstd;
    int wid = tid >> 5, lane = tid & 31;
    if (!lane) { rs[wid] = s; rss[wid] = ss; }
    __syncthreads();
    if (tid == 0) {
        float S = 0.f, SS = 0.f;
        #pragma unroll
        for (int i = 0; i < 8; ++i) { S += rs[i]; SS += rss[i]; }
        float mu = S / DIMN;
        s_mu = mu;
        s_rstd = rsqrtf(SS / DIMN - mu * mu + 1e-5f);
    }
    __syncthreads();
    float mu = s_mu, rstd = s_rstd;

    size_t base = (size_t)row * DIMN + tid * 8;
    uint32_t hw[4], lw[4];
    #pragma unroll
    for (int i = 0; i < 4; ++i) {
        int off = tid * 8 + 2 * i;
        float2 w2 = *(const float2*)(w + off);
        float2 b2 = *(const float2*)(bvec + off);
        float rx = (e[2 * i]     - mu) * rstd * w2.x + b2.x;
        float ry = (e[2 * i + 1] - mu) * rstd * w2.y + b2.y;
        pack_hilo(rx, ry, hw[i], lw[i]);
    }
    *(uint4*)(oh + base) = make_uint4(hw[0], hw[1], hw[2], hw[3]);
    *(uint4*)(ol + base) = make_uint4(lw[0], lw[1], lw[2], lw[3]);
}

// ---------------- shared GEMM mainloops (swizzled 64B rows) ------------------
#define TILE_B (128 * 64)        // 8192 bytes per operand tile
#define STAGE_B (4 * TILE_B)     // 32768 bytes per stage (3-term layout)

__device__ __forceinline__ void cp_tile(uint32_t sdst, const __half* __restrict__ g,
                                        int row0, int K, int k0) {
    int tid = threadIdx.x;
    const char* gb = (const char*)(g + (size_t)row0 * K + k0);
    size_t rb = (size_t)K * 2;
    #pragma unroll
    for (int j = 0; j < 2; ++j) {
        int lin = j * 256 + tid;
        int r = lin >> 2, c = lin & 3;
        cp16(sw64(sdst, r, c), gb + (size_t)r * rb + c * 16);
    }
}

// 3-term mainloop (2 stages): D += Ah Bh + Ah Bl + Al Bh
__device__ __forceinline__ void gemm_mainloop(
        const __half* __restrict__ Ah, const __half* __restrict__ Al,
        const __half* __restrict__ Bh, const __half* __restrict__ Bl,
        int row0, int col0, int K, uint32_t sb, float acc[4][4][4]) {
    int tid = threadIdx.x, lane = tid & 31, wid = tid >> 5;
    int wm = wid & 1, wn = wid >> 1;

    const int nst = K >> 5;
    cp_tile(sb,              Ah, row0, K, 0);
    cp_tile(sb + TILE_B,     Al, row0, K, 0);
    cp_tile(sb + 2 * TILE_B, Bh, col0, K, 0);
    cp_tile(sb + 3 * TILE_B, Bl, col0, K, 0);
    asm volatile("cp.async.commit_group;" ::: "memory");

    const int arow = wm * 64 + (lane & 15);
    const int ac   = lane >> 4;
    const int brow = wn * 32 + (lane & 7);
    const int bc   = ((lane >> 3) & 1) | ((lane >> 4) << 1);

    for (int i = 0; i < nst; ++i) {
        asm volatile("cp.async.wait_group 0;" ::: "memory");
        __syncthreads();

        if (i + 1 < nst) {
            uint32_t pst = sb + ((i + 1) & 1) * STAGE_B;
            int k0 = (i + 1) << 5;
            cp_tile(pst,              Ah, row0, K, k0);
            cp_tile(pst + TILE_B,     Al, row0, K, k0);
            cp_tile(pst + 2 * TILE_B, Bh, col0, K, k0);
            cp_tile(pst + 3 * TILE_B, Bl, col0, K, k0);
            asm volatile("cp.async.commit_group;" ::: "memory");
        }

        uint32_t st = sb + (i & 1) * STAGE_B;
        uint32_t bh[4][4], bl[4][4];
        #pragma unroll
        for (int ni = 0; ni < 4; ++ni) {
            ldmx4(bh[ni], sw64(st + 2 * TILE_B, brow + ni * 8, bc));
            ldmx4(bl[ni], sw64(st + 3 * TILE_B, brow + ni * 8, bc));
        }

        #pragma unroll
        for (int mi = 0; mi < 4; ++mi) {
            int row = arow + mi * 16;
            uint32_t ah0[4], al0[4], ah1[4], al1[4];
            ldmx4(ah0, sw64(st,          row, ac));
            ldmx4(al0, sw64(st + TILE_B, row, ac));
            ldmx4(ah1, sw64(st,          row, ac + 2));
            ldmx4(al1, sw64(st + TILE_B, row, ac + 2));
            #pragma unroll
            for (int ni = 0; ni < 4; ++ni) {
                mma16816(acc[mi][ni], ah0, bh[ni]);
                mma16816(acc[mi][ni], ah0, bl[ni]);
                mma16816(acc[mi][ni], al0, bh[ni]);
            }
            #pragma unroll
            for (int ni = 0; ni < 4; ++ni) {
                mma16816(acc[mi][ni], ah1, bh[ni] + 2);
                mma16816(acc[mi][ni], ah1, bl[ni] + 2);
                mma16816(acc[mi][ni], al1, bh[ni] + 2);
            }
        }
    }
    __syncthreads();
}

// 2-term mainloop (2 stages): D += Ah Bh + Al Bh  (B single fp16)
__device__ __forceinline__ void gemm_mainloop2(
        const __half* __restrict__ Ah, const __half* __restrict__ Al,
        const __half* __restrict__ Bh,
        int row0, int col0, int K, uint32_t sb, float acc[4][4][4]) {
    int tid = threadIdx.x, lane = tid & 31, wid = tid >> 5;
    int wm = wid & 1, wn = wid >> 1;

    const int nst = K >> 5;
    cp_tile(sb,              Ah, row0, K, 0);
    cp_tile(sb + TILE_B,     Al, row0, K, 0);
    cp_tile(sb + 2 * TILE_B, Bh, col0, K, 0);
    asm volatile("cp.async.commit_group;" ::: "memory");

    const int arow = wm * 64 + (lane & 15);
    const int ac   = lane >> 4;
    const int brow = wn * 32 + (lane & 7);
    const int bc   = ((lane >> 3) & 1) | ((lane >> 4) << 1);

    for (int i = 0; i < nst; ++i) {
        asm volatile("cp.async.wait_group 0;" ::: "memory");
        __syncthreads();

        if (i + 1 < nst) {
            uint32_t pst = sb + ((i + 1) & 1) * STAGE_B;
            int k0 = (i + 1) << 5;
            cp_tile(pst,              Ah, row0, K, k0);
            cp_tile(pst + TILE_B,     Al, row0, K, k0);
            cp_tile(pst + 2 * TILE_B, Bh, col0, K, k0);
            asm volatile("cp.async.commit_group;" ::: "memory");
        }

        uint32_t st = sb + (i & 1) * STAGE_B;
        uint32_t bh[4][4];
        #pragma unroll
        for (int ni = 0; ni < 4; ++ni)
            ldmx4(bh[ni], sw64(st + 2 * TILE_B, brow + ni * 8, bc));

        #pragma unroll
        for (int mi = 0; mi < 4; ++mi) {
            int row = arow + mi * 16;
            uint32_t ah0[4], al0[4], ah1[4], al1[4];
            ldmx4(ah0, sw64(st,          row, ac));
            ldmx4(al0, sw64(st + TILE_B, row, ac));
            ldmx4(ah1, sw64(st,          row, ac + 2));
            ldmx4(al1, sw64(st + TILE_B, row, ac + 2));
            #pragma unroll
            for (int ni = 0; ni < 4; ++ni) {
                mma16816(acc[mi][ni], ah0, bh[ni]);
                mma16816(acc[mi][ni], al0, bh[ni]);
            }
            #pragma unroll
            for (int ni = 0; ni < 4; ++ni) {
                mma16816(acc[mi][ni], ah1, bh[ni] + 2);
                mma16816(acc[mi][ni], al1, bh[ni] + 2);
            }
        }
    }
    __syncthreads();
}

// ---------------- merged QKV projection (one launch) ------------------------
// blockIdx.x: [0,16) -> Q (rope+scale, 3-term), [16,20) -> K (rope, 3-term),
//             [20,24) -> V (2-term, single fp16 out)
__global__ __launch_bounds__(256, 2)
void qkv_gemm(const float* __restrict__ fr, float qscale) {
    extern __shared__ char sm[];
    uint32_t sb = smem_to_u32(sm);
    int bx = blockIdx.x;
    int tid = threadIdx.x, lane = tid & 31, wid = tid >> 5;
    int wm = wid & 1, wn = wid >> 1;
    int row0 = blockIdx.y * 128;

    float acc[4][4][4];
    #pragma unroll
    for (int i = 0; i < 4; ++i)
        #pragma unroll
        for (int j = 0; j < 4; ++j)
            #pragma unroll
            for (int q = 0; q < 4; ++q) acc[i][j][q] = 0.f;

    __half *Oh, *Ol;
    int N, col0, do_rope;
    float scale;
    if (bx < 16) {
        Oh = g_qh; Ol = g_ql;
        N = DIMN; col0 = bx * 128; do_rope = 1; scale = qscale;
        gemm_mainloop(g_xn_h, g_xn_l, g_wq_h, g_wq_l, row0, col0, DIMN, sb, acc);
    } else if (bx < 20) {
        Oh = g_kh; Ol = g_kl;
        N = 512; col0 = (bx - 16) * 128; do_rope = 1; scale = 1.0f;
        gemm_mainloop(g_xn_h, g_xn_l, g_wk_h, g_wk_l, row0, col0, DIMN, sb, acc);
    } else {
        Oh = g_v; Ol = nullptr;
        N = 512; col0 = (bx - 20) * 128; do_rope = 0; scale = 1.0f;
        gemm_mainloop2(g_xn_h, g_xn_l, g_wv_h, row0, col0, DIMN, sb, acc);
    }

    int mrow = row0 + wm * 64 + (lane >> 2);
    int ncol = col0 + wn * 32 + (lane & 3) * 2;
    #pragma unroll
    for (int mi = 0; mi < 4; ++mi)
        #pragma unroll
        for (int ni = 0; ni < 4; ++ni) {
            int col = ncol + ni * 8;
            int r0 = mrow + mi * 16, r1 = r0 + 8;
            float x0 = acc[mi][ni][0], y0 = acc[mi][ni][1];
            float x1 = acc[mi][ni][2], y1 = acc[mi][ni][3];
            if (do_rope) {
                int fi = (col & 127) >> 1;
                int s0 = r0 & (S_LEN - 1), s1 = r1 & (S_LEN - 1);
                float c0 = fr[(s0 * 64 + fi) * 2], n0 = fr[(s0 * 64 + fi) * 2 + 1];
                float c1 = fr[(s1 * 64 + fi) * 2], n1 = fr[(s1 * 64 + fi) * 2 + 1];
                float tx0 = (x0 * c0 - y0 * n0) * scale;
                float ty0 = (x0 * n0 + y0 * c0) * scale;
                float tx1 = (x1 * c1 - y1 * n1) * scale;
                float ty1 = (x1 * n1 + y1 * c1) * scale;
                x0 = tx0; y0 = ty0; x1 = tx1; y1 = ty1;
            }
            uint32_t h0, l0, h1, l1;
            pack_hilo(x0, y0, h0, l0);
            pack_hilo(x1, y1, h1, l1);
            *(uint32_t*)(Oh + (size_t)r0 * N + col) = h0;
            *(uint32_t*)(Oh + (size_t)r1 * N + col) = h1;
            if (Ol) {
                *(uint32_t*)(Ol + (size_t)r0 * N + col) = l0;
                *(uint32_t*)(Ol + (size_t)r1 * N + col) = l1;
            }
        }
}

// ---------------- output projection: out = xn * wo^T (2-term fp16) ----------
__global__ __launch_bounds__(256, 2)
void o_gemm(float* __restrict__ C) {
    extern __shared__ char sm[];
    uint32_t sb = smem_to_u32(sm);
    int tid = threadIdx.x, lane = tid & 31, wid = tid >> 5;
    int wm = wid & 1, wn = wid >> 1;
    int row0 = blockIdx.y * 128, col0 = blockIdx.x * 128;

    float acc[4][4][4];
    #pragma unroll
    for (int i = 0; i < 4; ++i)
        #pragma unroll
        for (int j = 0; j < 4; ++j)
            #pragma unroll
            for (int q = 0; q < 4; ++q) acc[i][j][q] = 0.f;

    gemm_mainloop2(g_xn_h, g_xn_l, g_wo_h, row0, col0, DIMN, sb, acc);

    int mrow = row0 + wm * 64 + (lane >> 2);
    int ncol = col0 + wn * 32 + (lane & 3) * 2;
    #pragma unroll
    for (int mi = 0; mi < 4; ++mi)
        #pragma unroll
        for (int ni = 0; ni < 4; ++ni) {
            float* p0 = C + (size_t)(mrow + mi * 16) * DIMN + ncol + ni * 8;
            float* p1 = C + (size_t)(mrow + mi * 16 + 8) * DIMN + ncol + ni * 8;
            *(float2*)p0 = make_float2(acc[mi][ni][0], acc[mi][ni][1]);
            *(float2*)p1 = make_float2(acc[mi][ni][2], acc[mi][ni][3]);
        }
}

// ---------------- tensor-core flash attention --------------------------------
// QK 3-term (K frags via x4 covering k32); PV 1-term. Stage: Kh,Kl,V.
#define APITCH 272
#define ATILE  (64 * APITCH)     // 17408 bytes
#define QTILE  (128 * APITCH)    // 34816 bytes
#define KVSTAGE (3 * ATILE)

__device__ __forceinline__ void cp_kv(uint32_t dst, const __half* __restrict__ g,
                                      int b, int kvh, int row0) {
    int tid = threadIdx.x;
    #pragma unroll
    for (int j = 0; j < 4; ++j) {
        int lin = j * 256 + tid;
        int r = lin >> 4, c = lin & 15;
        const __half* s = g + (((size_t)(b * S_LEN + row0 + r)) * NKV + kvh) * HD + c * 8;
        cp16(dst + r * APITCH + c * 16, s);
    }
}

__global__ __launch_bounds__(256, 1)
void attn_kernel() {
    extern __shared__ char asm_[];
    uint32_t sb = smem_to_u32(asm_);
    const uint32_t smQh = sb;
    const uint32_t smQl = sb + QTILE;
    const uint32_t smKV = sb + 2 * QTILE;

    const int tid = threadIdx.x;
    const int lane = tid & 31, wid = tid >> 5;
    const int gid = lane >> 2, tig = lane & 3;
    const int qt = (int)gridDim.x - 1 - (int)blockIdx.x;   // largest-first
    const int q0 = qt * 128;
    const int h  = blockIdx.y;
    const int b  = blockIdx.z;
    const int kvh = h >> 2;
    const int m0 = wid * 16;
    const int nkt = 2 * (qt + 1);

    #pragma unroll
    for (int j = 0; j < 8; ++j) {
        int lin = j * 256 + tid;
        int r = lin >> 4, c = lin & 15;
        size_t go = (((size_t)(b * S_LEN + q0 + r)) * NH + h) * HD + c * 8;
        cp16(smQh + r * APITCH + c * 16, g_qh + go);
        cp16(smQl + r * APITCH + c * 16, g_ql + go);
    }
    cp_kv(smKV,             g_kh, b, kvh, 0);
    cp_kv(smKV + ATILE,     g_kl, b, kvh, 0);
    cp_kv(smKV + 2 * ATILE, g_v,  b, kvh, 0);
    asm volatile("cp.async.commit_group;" ::: "memory");
    {
        uint32_t st = smKV + KVSTAGE;
        cp_kv(st,             g_kh, b, kvh, 64);
        cp_kv(st + ATILE,     g_kl, b, kvh, 64);
        cp_kv(st + 2 * ATILE, g_v,  b, kvh, 64);
        asm volatile("cp.async.commit_group;" ::: "memory");
    }

    const int qg0 = q0 + m0 + gid;
    const int qg1 = qg0 + 8;
    const int qmax = q0 + m0 + 15;
    const int csq0 = (qg0 > 0) ? g_cs[b * S_LEN + qg0 - 1] : 0;
    const int csq1 = g_cs[b * S_LEN + qg1 - 1];

    float oacc[16][4];
    #pragma unroll
    for (int d = 0; d < 16; ++d)
        #pragma unroll
        for (int q = 0; q < 4; ++q) oacc[d][q] = 0.f;
    float mrow0 = -1e30f, mrow1 = -1e30f, lrow0 = 0.f, lrow1 = 0.f;

    for (int it = 0; it < nkt; ++it) {
        const int k0 = it * 64;
        if (it + 1 < nkt) asm volatile("cp.async.wait_group 1;" ::: "memory");
        else              asm volatile("cp.async.wait_group 0;" ::: "memory");
        __syncthreads();

        if (k0 <= qmax) {
            const uint32_t st  = smKV + (it & 1) * KVSTAGE;
            const uint32_t sKh = st, sKl = st + ATILE, sV = st + 2 * ATILE;

            float sacc[8][4];
            #pragma unroll
            for (int j = 0; j < 8; ++j)
                #pragma unroll
                for (int q = 0; q < 4; ++q) sacc[j][q] = 0.f;

            const uint32_t qoff = (m0 + (lane & 15)) * APITCH + (lane >> 4) * 16;
            const uint32_t koff = (lane & 7) * APITCH + (lane >> 3) * 16;  // x4: k32
            #pragma unroll
            for (int kk2 = 0; kk2 < 4; ++kk2) {
                uint32_t qh0[4], ql0[4], qh1[4], ql1[4];
                uint32_t qa = qoff + kk2 * 64;
                ldmx4(qh0, smQh + qa);
                ldmx4(ql0, smQl + qa);
                ldmx4(qh1, smQh + qa + 32);
                ldmx4(ql1, smQl + qa + 32);
                #pragma unroll
                for (int j = 0; j < 8; ++j) {
                    uint32_t kh[4], kl[4];
                    uint32_t ka = koff + j * 8 * APITCH + kk2 * 64;
                    ldmx4(kh, sKh + ka);
                    ldmx4(kl, sKl + ka);
                    mma16816(sacc[j], qh0, kh);
                    mma16816(sacc[j], qh0, kl);
                    mma16816(sacc[j], ql0, kh);
                    mma16816(sacc[j], qh1, kh + 2);
                    mma16816(sacc[j], qh1, kl + 2);
                    mma16816(sacc[j], ql1, kh + 2);
                }
            }

            if (k0 + 73 >= q0 + m0) {
                #pragma unroll
                for (int j = 0; j < 8; ++j) {
                    int kg0 = k0 + j * 8 + tig * 2;
                    int kg1 = kg0 + 1;
                    int bi0 = kg0 + 10; if (bi0 > S_LEN - 1) bi0 = S_LEN - 1;
                    int bi1 = kg1 + 10; if (bi1 > S_LEN - 1) bi1 = S_LEN - 1;
                    int ck0 = g_cs[b * S_LEN + bi0];
                    int ck1 = g_cs[b * S_LEN + bi1];
                    if (kg0 + 10 >= qg0 && ck0 - csq0 > 0) sacc[j][0] += 2.0f;
                    if (kg1 + 10 >= qg0 && ck1 - csq0 > 0) sacc[j][1] += 2.0f;
                    if (kg0 + 10 >= qg1 && ck0 - csq1 > 0) sacc[j][2] += 2.0f;
                    if (kg1 + 10 >= qg1 && ck1 - csq1 > 0) sacc[j][3] += 2.0f;
                }
            }
            if (k0 + 63 > qg0) {
                #pragma unroll
                for (int j = 0; j < 8; ++j) {
                    int kg0 = k0 + j * 8 + tig * 2;
                    int kg1 = kg0 + 1;
                    if (kg0 > qg0) sacc[j][0] = -1e9f;
                    if (kg1 > qg0) sacc[j][1] = -1e9f;
                    if (kg0 > qg1) sacc[j][2] = -1e9f;
                    if (kg1 > qg1) sacc[j][3] = -1e9f;
                }
            }

            float mx0 = -1e30f, mx1 = -1e30f;
            #pragma unroll
            for (int j = 0; j < 8; ++j) {
                mx0 = fmaxf(mx0, fmaxf(sacc[j][0], sacc[j][1]));
                mx1 = fmaxf(mx1, fmaxf(sacc[j][2], sacc[j][3]));
            }
            mx0 = fmaxf(mx0, __shfl_xor_sync(0xffffffffu, mx0, 1));
            mx0 = fmaxf(mx0, __shfl_xor_sync(0xffffffffu, mx0, 2));
            mx1 = fmaxf(mx1, __shfl_xor_sync(0xffffffffu, mx1, 1));
            mx1 = fmaxf(mx1, __shfl_xor_sync(0xffffffffu, mx1, 2));
            float mn0 = fmaxf(mrow0, mx0), mn1 = fmaxf(mrow1, mx1);
            float a0 = __expf(mrow0 - mn0), a1 = __expf(mrow1 - mn1);
            mrow0 = mn0; mrow1 = mn1;
            float sum0 = 0.f, sum1 = 0.f;
            #pragma unroll
            for (int j = 0; j < 8; ++j) {
                sacc[j][0] = __expf(sacc[j][0] - mn0); sum0 += sacc[j][0];
                sacc[j][1] = __expf(sacc[j][1] - mn0); sum0 += sacc[j][1];
                sacc[j][2] = __expf(sacc[j][2] - mn1); sum1 += sacc[j][2];
                sacc[j][3] = __expf(sacc[j][3] - mn1); sum1 += sacc[j][3];
            }
            sum0 += __shfl_xor_sync(0xffffffffu, sum0, 1);
            sum0 += __shfl_xor_sync(0xffffffffu, sum0, 2);
            sum1 += __shfl_xor_sync(0xffffffffu, sum1, 1);
            sum1 += __shfl_xor_sync(0xffffffffu, sum1, 2);
            lrow0 = lrow0 * a0 + sum0;
            lrow1 = lrow1 * a1 + sum1;
            #pragma unroll
            for (int d = 0; d < 16; ++d) {
                oacc[d][0] *= a0; oacc[d][1] *= a0;
                oacc[d][2] *= a1; oacc[d][3] *= a1;
            }

            uint32_t ph[4][4];
            #pragma unroll
            for (int t = 0; t < 4; ++t) {
                int j0 = 2 * t, j1 = 2 * t + 1;
                ph[t][0] = pack_h(sacc[j0][0], sacc[j0][1]);
                ph[t][1] = pack_h(sacc[j0][2], sacc[j0][3]);
                ph[t][2] = pack_h(sacc[j1][0], sacc[j1][1]);
                ph[t][3] = pack_h(sacc[j1][2], sacc[j1][3]);
            }

            const uint32_t voff = (lane & 15) * APITCH + (lane >> 4) * 16;
            #pragma unroll
            for (int t = 0; t < 4; ++t) {
                #pragma unroll
                for (int dn2 = 0; dn2 < 8; ++dn2) {
                    uint32_t vh[4];
                    ldmx4t(vh, sV + voff + t * 16 * APITCH + dn2 * 32);
                    mma16816(oacc[2 * dn2],     ph[t], vh);
                    mma16816(oacc[2 * dn2 + 1], ph[t], vh + 2);
                }
            }
        }
        __syncthreads();

        if (it + 2 < nkt) {
            uint32_t pst = smKV + (it & 1) * KVSTAGE;
            int row0 = (it + 2) * 64;
            cp_kv(pst,             g_kh, b, kvh, row0);
            cp_kv(pst + ATILE,     g_kl, b, kvh, row0);
            cp_kv(pst + 2 * ATILE, g_v,  b, kvh, row0);
            asm volatile("cp.async.commit_group;" ::: "memory");
        }
    }

    float il0 = 1.0f / lrow0, il1 = 1.0f / lrow1;
    size_t b0 = (((size_t)(b * S_LEN + qg0)) * NH + h) * HD + tig * 2;
    size_t b1 = (((size_t)(b * S_LEN + qg1)) * NH + h) * HD + tig * 2;
    #pragma unroll
    for (int d = 0; d < 16; ++d) {
        *(uint32_t*)(g_ao + b0 + d * 8) = pack_h(oacc[d][0] * il0, oacc[d][1] * il0);
        *(uint32_t*)(g_ao + b1 + d * 8) = pack_h(oacc[d][2] * il1, oacc[d][3] * il1);
    }
}

// ---------------- launch ----------------------------------------------------
extern "C" void kernel_launch(void* const* d_in, const int* in_sizes, int n_in,
                              void* d_out, int out_size) {
    const float* x      = (const float*)d_in[0];
    const float* freqs  = (const float*)d_in[2];
    const int*   labels = (const int*)d_in[4];
    const float* wq     = (const float*)d_in[5];
    const float* wk     = (const float*)d_in[6];
    const float* wv     = (const float*)d_in[7];
    const float* wo     = (const float*)d_in[8];
    const float* ln1w   = (const float*)d_in[9];
    const float* ln1b   = (const float*)d_in[10];
    const float* ln2w   = (const float*)d_in[11];
    const float* ln2b   = (const float*)d_in[12];
    float* out = (float*)d_out;

    __half *xnh, *xnl, *ao;
    cudaGetSymbolAddress((void**)&xnh, g_xn_h);
    cudaGetSymbolAddress((void**)&xnl, g_xn_l);
    cudaGetSymbolAddress((void**)&ao,  g_ao);

    split_all<<<TOT_F4 / 1024, 256>>>(wq, wk, wv, wo);
    ln_kernel<<<ROWS, 256>>>(x, ln1w, ln1b, xnh, xnl);
    cumsum_kernel<<<2, 1024>>>(labels);

    size_t gemm_smem = 2 * STAGE_B;   // 65536 — keeps large L1 carveout
    cudaFuncSetAttribute(qkv_gemm, cudaFuncAttributeMaxDynamicSharedMemorySize, (int)gemm_smem);
    cudaFuncSetAttribute(o_gemm, cudaFuncAttributeMaxDynamicSharedMemorySize, (int)gemm_smem);

    const float qscale = 0.08838834764831845f;   // 1/sqrt(128)
    qkv_gemm<<<dim3(24, ROWS / 128), 256, gemm_smem>>>(freqs, qscale);

    size_t attn_smem = 2 * QTILE + 2 * KVSTAGE;   // 174080
    cudaFuncSetAttribute(attn_kernel, cudaFuncAttributeMaxDynamicSharedMemorySize,
                         (int)attn_smem);
    attn_kernel<<<dim3(S_LEN / 128, NH, 2), 256, attn_smem>>>();

    ln_kernel_h<<<ROWS, 256>>>(ao, ln2w, ln2b, xnh, xnl);
    o_gemm<<<dim3(DIMN / 128, ROWS / 128), 256, gemm_smem>>>(out);
}

// round 16
// speedup vs baseline: 1.1534x; 1.0951x over previous
#include <cuda_runtime.h>
#include <cuda_fp16.h>
#include <math.h>
#include <stdint.h>

#define S_LEN 2048
#define DIMN  2048
#define NH    16
#define NKV   4
#define HD    128
#define ROWS  4096   // B*S

// ---------------- scratch (device globals; no allocation allowed) ----------
__device__ __half g_xn_h[ROWS * DIMN];
__device__ __half g_xn_l[ROWS * DIMN];
__device__ __half g_wq_h[DIMN * DIMN];
__device__ __half g_wq_l[DIMN * DIMN];
__device__ __half g_wk_h[512 * DIMN];
__device__ __half g_wk_l[512 * DIMN];
__device__ __half g_wv_h[512 * DIMN];    // single fp16 (1-term V proj)
__device__ __half g_wo_h[DIMN * DIMN];   // single fp16 (1-term o_gemm)
__device__ __half g_qh[ROWS * DIMN];  // roped+scaled Q hi/lo
__device__ __half g_ql[ROWS * DIMN];
__device__ __half g_kh[ROWS * 512];   // roped K hi/lo
__device__ __half g_kl[ROWS * 512];
__device__ __half g_v [ROWS * 512];   // V single fp16
__device__ __half g_ao[ROWS * DIMN];  // attention output, fp16
__device__ int   g_cs[2 * S_LEN];     // per-batch inclusive cumsum of labels

// ---------------- helpers ----------------------------------------------------
__device__ __forceinline__ uint32_t smem_to_u32(const void* p) {
    uint32_t a;
    asm("{ .reg .u64 t; cvta.to.shared.u64 t, %1; cvt.u32.u64 %0, t; }" : "=r"(a) : "l"(p));
    return a;
}
__device__ __forceinline__ void ldmx4(uint32_t* r, uint32_t addr) {
    asm volatile("ldmatrix.sync.aligned.m8n8.x4.shared.b16 {%0,%1,%2,%3}, [%4];"
        : "=r"(r[0]), "=r"(r[1]), "=r"(r[2]), "=r"(r[3]) : "r"(addr));
}
__device__ __forceinline__ void ldmx4t(uint32_t* r, uint32_t addr) {
    asm volatile("ldmatrix.sync.aligned.m8n8.x4.trans.shared.b16 {%0,%1,%2,%3}, [%4];"
        : "=r"(r[0]), "=r"(r[1]), "=r"(r[2]), "=r"(r[3]) : "r"(addr));
}
__device__ __forceinline__ void mma16816(float* c, const uint32_t* a, const uint32_t* b) {
    asm volatile(
        "mma.sync.aligned.m16n8k16.row.col.f32.f16.f16.f32 "
        "{%0,%1,%2,%3}, {%4,%5,%6,%7}, {%8,%9}, {%0,%1,%2,%3};"
        : "+f"(c[0]), "+f"(c[1]), "+f"(c[2]), "+f"(c[3])
        : "r"(a[0]), "r"(a[1]), "r"(a[2]), "r"(a[3]), "r"(b[0]), "r"(b[1]));
}
__device__ __forceinline__ void cp16(uint32_t d, const void* s) {
    asm volatile("cp.async.ca.shared.global [%0], [%1], 16;" :: "r"(d), "l"(s));
}
__device__ __forceinline__ void pack_hilo(float x, float y, uint32_t& h, uint32_t& l) {
    __half2 hb = __floats2half2_rn(x, y);
    float rx = x - __low2float(hb);
    float ry = y - __high2float(hb);
    __half2 lb = __floats2half2_rn(rx, ry);
    h = *(uint32_t*)&hb;
    l = *(uint32_t*)&lb;
}
__device__ __forceinline__ uint32_t pack_h(float x, float y) {
    __half2 hb = __floats2half2_rn(x, y);
    return *(uint32_t*)&hb;
}

// swizzled smem address: 64B rows of 4x16B chunks, chunk ^= (row>>1)&3
__device__ __forceinline__ uint32_t sw64(uint32_t base, int row, int chunk) {
    return base + row * 64 + ((chunk ^ ((row >> 1) & 3)) << 4);
}

// ---------------- cumsum of seizure labels (per batch) ---------------------
__global__ void cumsum_kernel(const int* __restrict__ labels) {
    __shared__ int bufA[S_LEN], bufB[S_LEN];
    int b = blockIdx.x;
    for (int i = threadIdx.x; i < S_LEN; i += blockDim.x)
        bufA[i] = labels[b * S_LEN + i];
    __syncthreads();
    int* src = bufA; int* dst = bufB;
    for (int off = 1; off < S_LEN; off <<= 1) {
        for (int i = threadIdx.x; i < S_LEN; i += blockDim.x)
            dst[i] = src[i] + (i >= off ? src[i - off] : 0);
        __syncthreads();
        int* t = src; src = dst; dst = t;
    }
    for (int i = threadIdx.x; i < S_LEN; i += blockDim.x)
        g_cs[b * S_LEN + i] = src[i];
}

// ---------------- merged weight split: 4 float4 per thread (MLP=4) ----------
#define WQ_F4 1048576   // 2048*2048/4
#define WK_F4 262144    // 512*2048/4
#define WV_F4 262144
#define WO_F4 1048576
#define TOT_F4 (WQ_F4 + WK_F4 + WV_F4 + WO_F4)

__global__ void split_all(const float* __restrict__ wq, const float* __restrict__ wk,
                          const float* __restrict__ wv, const float* __restrict__ wo) {
    int blk0 = blockIdx.x * 1024;
    const float* src; __half *hi, *lo; int base;
    if (blk0 < WQ_F4) { src = wq; hi = g_wq_h; lo = g_wq_l; base = 0; }
    else if (blk0 < WQ_F4 + WK_F4) { src = wk; hi = g_wk_h; lo = g_wk_l; base = WQ_F4; }
    else if (blk0 < WQ_F4 + WK_F4 + WV_F4) { src = wv; hi = g_wv_h; lo = nullptr; base = WQ_F4 + WK_F4; }
    else { src = wo; hi = g_wo_h; lo = nullptr; base = WQ_F4 + WK_F4 + WV_F4; }
    int j0 = blk0 - base + threadIdx.x;

    float4 v[4];
    #pragma unroll
    for (int t = 0; t < 4; ++t)
        v[t] = ((const float4*)src)[j0 + t * 256];
    #pragma unroll
    for (int t = 0; t < 4; ++t) {
        int j = j0 + t * 256;
        uint32_t h01, h23, l01, l23;
        pack_hilo(v[t].x, v[t].y, h01, l01);
        pack_hilo(v[t].z, v[t].w, h23, l23);
        *(uint2*)(hi + (size_t)j * 4) = make_uint2(h01, h23);
        if (lo) *(uint2*)(lo + (size_t)j * 4) = make_uint2(l01, l23);
    }
}

// ---------------- layernorm (fp32 in) -> fp16 hi/lo --------------------------
__global__ void ln_kernel(const float* __restrict__ in, const float* __restrict__ w,
                          const float* __restrict__ bvec,
                          __half* __restrict__ oh, __half* __restrict__ ol) {
    int row = blockIdx.x;
    const float* x = in + (size_t)row * DIMN;
    int tid = threadIdx.x;

    float4 v0 = *(const float4*)(x + tid * 4);
    float4 v1 = *(const float4*)(x + 1024 + tid * 4);
    float s  = v0.x + v0.y + v0.z + v0.w + v1.x + v1.y + v1.z + v1.w;
    float ss = v0.x*v0.x + v0.y*v0.y + v0.z*v0.z + v0.w*v0.w
             + v1.x*v1.x + v1.y*v1.y + v1.z*v1.z + v1.w*v1.w;
    #pragma unroll
    for (int off = 16; off; off >>= 1) {
        s  += __shfl_xor_sync(0xffffffffu, s,  off);
        ss += __shfl_xor_sync(0xffffffffu, ss, off);
    }
    __shared__ float rs[8], rss[8];
    __shared__ float s_mu, s_rstd;
    int wid = tid >> 5, lane = tid & 31;
    if (!lane) { rs[wid] = s; rss[wid] = ss; }
    __syncthreads();
    if (tid == 0) {
        float S = 0.f, SS = 0.f;
        #pragma unroll
        for (int i = 0; i < 8; ++i) { S += rs[i]; SS += rss[i]; }
        float mu = S / DIMN;
        s_mu = mu;
        s_rstd = rsqrtf(SS / DIMN - mu * mu + 1e-5f);
    }
    __syncthreads();
    float mu = s_mu, rstd = s_rstd;

    size_t base = (size_t)row * DIMN;
    #pragma unroll
    for (int half = 0; half < 2; ++half) {
        int off = half * 1024 + tid * 4;
        float4 v = half ? v1 : v0;
        float4 w4 = *(const float4*)(w + off);
        float4 b4 = *(const float4*)(bvec + off);
        float4 r;
        r.x = (v.x - mu) * rstd * w4.x + b4.x;
        r.y = (v.y - mu) * rstd * w4.y + b4.y;
        r.z = (v.z - mu) * rstd * w4.z + b4.z;
        r.w = (v.w - mu) * rstd * w4.w + b4.w;
        uint32_t h01, h23, l01, l23;
        pack_hilo(r.x, r.y, h01, l01);
        pack_hilo(r.z, r.w, h23, l23);
        *(uint2*)(oh + base + off) = make_uint2(h01, h23);
        *(uint2*)(ol + base + off) = make_uint2(l01, l23);
    }
}

// ---------------- layernorm (fp16 in) -> fp16 hi/lo --------------------------
__global__ void ln_kernel_h(const __half* __restrict__ in, const float* __restrict__ w,
                            const float* __restrict__ bvec,
                            __half* __restrict__ oh, __half* __restrict__ ol) {
    int row = blockIdx.x;
    const __half* x = in + (size_t)row * DIMN;
    int tid = threadIdx.x;

    uint4 u = *(const uint4*)(x + tid * 8);
    __half2 hv[4] = {*(__half2*)&u.x, *(__half2*)&u.y, *(__half2*)&u.z, *(__half2*)&u.w};
    float e[8];
    #pragma unroll
    for (int i = 0; i < 4; ++i) {
        float2 f = __half22float2(hv[i]);
        e[2 * i] = f.x; e[2 * i + 1] = f.y;
    }
    float s = 0.f, ss = 0.f;
    #pragma unroll
    for (int i = 0; i < 8; ++i) { s += e[i]; ss += e[i] * e[i]; }
    #pragma unroll
    for (int off = 16; off; off >>= 1) {
        s  += __shfl_xor_sync(0xffffffffu, s,  off);
        ss += __shfl_xor_sync(0xffffffffu, ss, off);
    }
    __shared__ float rs[8], rss[8];
    __shared__ float s_mu, s_rstd;
    int wid = tid >> 5, lane = tid & 31;
    if (!lane) { rs[wid] = s; rss[wid] = ss; }
    __syncthreads();
    if (tid == 0) {
        float S = 0.f, SS = 0.f;
        #pragma unroll
        for (int i = 0; i < 8; ++i) { S += rs[i]; SS += rss[i]; }
        float mu = S / DIMN;
        s_mu = mu;
        s_rstd = rsqrtf(SS / DIMN - mu * mu + 1e-5f);
    }
    __syncthreads();
    float mu = s_mu, rstd = s_rstd;

    size_t base = (size_t)row * DIMN + tid * 8;
    uint32_t hw[4], lw[4];
    #pragma unroll
    for (int i = 0; i < 4; ++i) {
        int off = tid * 8 + 2 * i;
        float2 w2 = *(const float2*)(w + off);
        float2 b2 = *(const float2*)(bvec + off);
        float rx = (e[2 * i]     - mu) * rstd * w2.x + b2.x;
        float ry = (e[2 * i + 1] - mu) * rstd * w2.y + b2.y;
        pack_hilo(rx, ry, hw[i], lw[i]);
    }
    *(uint4*)(oh + base) = make_uint4(hw[0], hw[1], hw[2], hw[3]);
    *(uint4*)(ol + base) = make_uint4(lw[0], lw[1], lw[2], lw[3]);
}

// ---------------- shared GEMM mainloops (swizzled 64B rows) ------------------
#define TILE_B (128 * 64)        // 8192 bytes per operand tile
#define STAGE_B (4 * TILE_B)     // 32768 bytes per stage (3-term layout)
#define STAGE1_B (2 * TILE_B)    // 16384 bytes per stage (1-term layout)

__device__ __forceinline__ void cp_tile(uint32_t sdst, const __half* __restrict__ g,
                                        int row0, int K, int k0) {
    int tid = threadIdx.x;
    const char* gb = (const char*)(g + (size_t)row0 * K + k0);
    size_t rb = (size_t)K * 2;
    #pragma unroll
    for (int j = 0; j < 2; ++j) {
        int lin = j * 256 + tid;
        int r = lin >> 2, c = lin & 3;
        cp16(sw64(sdst, r, c), gb + (size_t)r * rb + c * 16);
    }
}

// 3-term mainloop (2 stages): D += Ah Bh + Ah Bl + Al Bh
__device__ __forceinline__ void gemm_mainloop(
        const __half* __restrict__ Ah, const __half* __restrict__ Al,
        const __half* __restrict__ Bh, const __half* __restrict__ Bl,
        int row0, int col0, int K, uint32_t sb, float acc[4][4][4]) {
    int tid = threadIdx.x, lane = tid & 31, wid = tid >> 5;
    int wm = wid & 1, wn = wid >> 1;

    const int nst = K >> 5;
    cp_tile(sb,              Ah, row0, K, 0);
    cp_tile(sb + TILE_B,     Al, row0, K, 0);
    cp_tile(sb + 2 * TILE_B, Bh, col0, K, 0);
    cp_tile(sb + 3 * TILE_B, Bl, col0, K, 0);
    asm volatile("cp.async.commit_group;" ::: "memory");

    const int arow = wm * 64 + (lane & 15);
    const int ac   = lane >> 4;
    const int brow = wn * 32 + (lane & 7);
    const int bc   = ((lane >> 3) & 1) | ((lane >> 4) << 1);

    for (int i = 0; i < nst; ++i) {
        asm volatile("cp.async.wait_group 0;" ::: "memory");
        __syncthreads();

        if (i + 1 < nst) {
            uint32_t pst = sb + ((i + 1) & 1) * STAGE_B;
            int k0 = (i + 1) << 5;
            cp_tile(pst,              Ah, row0, K, k0);
            cp_tile(pst + TILE_B,     Al, row0, K, k0);
            cp_tile(pst + 2 * TILE_B, Bh, col0, K, k0);
            cp_tile(pst + 3 * TILE_B, Bl, col0, K, k0);
            asm volatile("cp.async.commit_group;" ::: "memory");
        }

        uint32_t st = sb + (i & 1) * STAGE_B;
        uint32_t bh[4][4], bl[4][4];
        #pragma unroll
        for (int ni = 0; ni < 4; ++ni) {
            ldmx4(bh[ni], sw64(st + 2 * TILE_B, brow + ni * 8, bc));
            ldmx4(bl[ni], sw64(st + 3 * TILE_B, brow + ni * 8, bc));
        }

        #pragma unroll
        for (int mi = 0; mi < 4; ++mi) {
            int row = arow + mi * 16;
            uint32_t ah0[4], al0[4], ah1[4], al1[4];
            ldmx4(ah0, sw64(st,          row, ac));
            ldmx4(al0, sw64(st + TILE_B, row, ac));
            ldmx4(ah1, sw64(st,          row, ac + 2));
            ldmx4(al1, sw64(st + TILE_B, row, ac + 2));
            #pragma unroll
            for (int ni = 0; ni < 4; ++ni) {
                mma16816(acc[mi][ni], ah0, bh[ni]);
                mma16816(acc[mi][ni], ah0, bl[ni]);
                mma16816(acc[mi][ni], al0, bh[ni]);
            }
            #pragma unroll
            for (int ni = 0; ni < 4; ++ni) {
                mma16816(acc[mi][ni], ah1, bh[ni] + 2);
                mma16816(acc[mi][ni], ah1, bl[ni] + 2);
                mma16816(acc[mi][ni], al1, bh[ni] + 2);
            }
        }
    }
    __syncthreads();
}

// 1-term mainloop (2 stages): D += Ah Bh  (A and B single fp16)
__device__ __forceinline__ void gemm_mainloop1(
        const __half* __restrict__ Ah, const __half* __restrict__ Bh,
        int row0, int col0, int K, uint32_t sb, float acc[4][4][4]) {
    int tid = threadIdx.x, lane = tid & 31, wid = tid >> 5;
    int wm = wid & 1, wn = wid >> 1;

    const int nst = K >> 5;
    cp_tile(sb,          Ah, row0, K, 0);
    cp_tile(sb + TILE_B, Bh, col0, K, 0);
    asm volatile("cp.async.commit_group;" ::: "memory");

    const int arow = wm * 64 + (lane & 15);
    const int ac   = lane >> 4;
    const int brow = wn * 32 + (lane & 7);
    const int bc   = ((lane >> 3) & 1) | ((lane >> 4) << 1);

    for (int i = 0; i < nst; ++i) {
        asm volatile("cp.async.wait_group 0;" ::: "memory");
        __syncthreads();

        if (i + 1 < nst) {
            uint32_t pst = sb + ((i + 1) & 1) * STAGE1_B;
            int k0 = (i + 1) << 5;
            cp_tile(pst,          Ah, row0, K, k0);
            cp_tile(pst + TILE_B, Bh, col0, K, k0);
            asm volatile("cp.async.commit_group;" ::: "memory");
        }

        uint32_t st = sb + (i & 1) * STAGE1_B;
        uint32_t bh[4][4];
        #pragma unroll
        for (int ni = 0; ni < 4; ++ni)
            ldmx4(bh[ni], sw64(st + TILE_B, brow + ni * 8, bc));

        #pragma unroll
        for (int mi = 0; mi < 4; ++mi) {
            int row = arow + mi * 16;
            uint32_t ah0[4], ah1[4];
            ldmx4(ah0, sw64(st, row, ac));
            ldmx4(ah1, sw64(st, row, ac + 2));
            #pragma unroll
            for (int ni = 0; ni < 4; ++ni) {
                mma16816(acc[mi][ni], ah0, bh[ni]);
                mma16816(acc[mi][ni], ah1, bh[ni] + 2);
            }
        }
    }
    __syncthreads();
}

// ---------------- merged QKV projection (one launch) ------------------------
// blockIdx.x: [0,16) -> Q (rope+scale, 3-term), [16,20) -> K (rope, 3-term),
//             [20,24) -> V (1-term, single fp16 out)
__global__ __launch_bounds__(256, 2)
void qkv_gemm(const float* __restrict__ fr, float qscale) {
    extern __shared__ char sm[];
    uint32_t sb = smem_to_u32(sm);
    int bx = blockIdx.x;
    int tid = threadIdx.x, lane = tid & 31, wid = tid >> 5;
    int wm = wid & 1, wn = wid >> 1;
    int row0 = blockIdx.y * 128;

    float acc[4][4][4];
    #pragma unroll
    for (int i = 0; i < 4; ++i)
        #pragma unroll
        for (int j = 0; j < 4; ++j)
            #pragma unroll
            for (int q = 0; q < 4; ++q) acc[i][j][q] = 0.f;

    __half *Oh, *Ol;
    int N, col0, do_rope;
    float scale;
    if (bx < 16) {
        Oh = g_qh; Ol = g_ql;
        N = DIMN; col0 = bx * 128; do_rope = 1; scale = qscale;
        gemm_mainloop(g_xn_h, g_xn_l, g_wq_h, g_wq_l, row0, col0, DIMN, sb, acc);
    } else if (bx < 20) {
        Oh = g_kh; Ol = g_kl;
        N = 512; col0 = (bx - 16) * 128; do_rope = 1; scale = 1.0f;
        gemm_mainloop(g_xn_h, g_xn_l, g_wk_h, g_wk_l, row0, col0, DIMN, sb, acc);
    } else {
        Oh = g_v; Ol = nullptr;
        N = 512; col0 = (bx - 20) * 128; do_rope = 0; scale = 1.0f;
        gemm_mainloop1(g_xn_h, g_wv_h, row0, col0, DIMN, sb, acc);
    }

    int mrow = row0 + wm * 64 + (lane >> 2);
    int ncol = col0 + wn * 32 + (lane & 3) * 2;
    #pragma unroll
    for (int mi = 0; mi < 4; ++mi)
        #pragma unroll
        for (int ni = 0; ni < 4; ++ni) {
            int col = ncol + ni * 8;
            int r0 = mrow + mi * 16, r1 = r0 + 8;
            float x0 = acc[mi][ni][0], y0 = acc[mi][ni][1];
            float x1 = acc[mi][ni][2], y1 = acc[mi][ni][3];
            if (do_rope) {
                int fi = (col & 127) >> 1;
                int s0 = r0 & (S_LEN - 1), s1 = r1 & (S_LEN - 1);
                float c0 = fr[(s0 * 64 + fi) * 2], n0 = fr[(s0 * 64 + fi) * 2 + 1];
                float c1 = fr[(s1 * 64 + fi) * 2], n1 = fr[(s1 * 64 + fi) * 2 + 1];
                float tx0 = (x0 * c0 - y0 * n0) * scale;
                float ty0 = (x0 * n0 + y0 * c0) * scale;
                float tx1 = (x1 * c1 - y1 * n1) * scale;
                float ty1 = (x1 * n1 + y1 * c1) * scale;
                x0 = tx0; y0 = ty0; x1 = tx1; y1 = ty1;
            }
            uint32_t h0, l0, h1, l1;
            pack_hilo(x0, y0, h0, l0);
            pack_hilo(x1, y1, h1, l1);
            *(uint32_t*)(Oh + (size_t)r0 * N + col) = h0;
            *(uint32_t*)(Oh + (size_t)r1 * N + col) = h1;
            if (Ol) {
                *(uint32_t*)(Ol + (size_t)r0 * N + col) = l0;
                *(uint32_t*)(Ol + (size_t)r1 * N + col) = l1;
            }
        }
}

// ---------------- output projection: out = xn_h * wo_h^T (1-term fp16) ------
__global__ __launch_bounds__(256, 2)
void o_gemm(float* __restrict__ C) {
    extern __shared__ char sm[];
    uint32_t sb = smem_to_u32(sm);
    int tid = threadIdx.x, lane = tid & 31, wid = tid >> 5;
    int wm = wid & 1, wn = wid >> 1;
    int row0 = blockIdx.y * 128, col0 = blockIdx.x * 128;

    float acc[4][4][4];
    #pragma unroll
    for (int i = 0; i < 4; ++i)
        #pragma unroll
        for (int j = 0; j < 4; ++j)
            #pragma unroll
            for (int q = 0; q < 4; ++q) acc[i][j][q] = 0.f;

    gemm_mainloop1(g_xn_h, g_wo_h, row0, col0, DIMN, sb, acc);

    int mrow = row0 + wm * 64 + (lane >> 2);
    int ncol = col0 + wn * 32 + (lane & 3) * 2;
    #pragma unroll
    for (int mi = 0; mi < 4; ++mi)
        #pragma unroll
        for (int ni = 0; ni < 4; ++ni) {
            float* p0 = C + (size_t)(mrow + mi * 16) * DIMN + ncol + ni * 8;
            float* p1 = C + (size_t)(mrow + mi * 16 + 8) * DIMN + ncol + ni * 8;
            *(float2*)p0 = make_float2(acc[mi][ni][0], acc[mi][ni][1]);
            *(float2*)p1 = make_float2(acc[mi][ni][2], acc[mi][ni][3]);
        }
}

// ---------------- tensor-core flash attention --------------------------------
// QK 3-term (K frags via x4 covering k32); PV 1-term. Stage: Kh,Kl,V.
#define APITCH 272
#define ATILE  (64 * APITCH)     // 17408 bytes
#define QTILE  (128 * APITCH)    // 34816 bytes
#define KVSTAGE (3 * ATILE)

__device__ __forceinline__ void cp_kv(uint32_t dst, const __half* __restrict__ g,
                                      int b, int kvh, int row0) {
    int tid = threadIdx.x;
    #pragma unroll
    for (int j = 0; j < 4; ++j) {
        int lin = j * 256 + tid;
        int r = lin >> 4, c = lin & 15;
        const __half* s = g + (((size_t)(b * S_LEN + row0 + r)) * NKV + kvh) * HD + c * 8;
        cp16(dst + r * APITCH + c * 16, s);
    }
}

__global__ __launch_bounds__(256, 1)
void attn_kernel() {
    extern __shared__ char asm_[];
    uint32_t sb = smem_to_u32(asm_);
    const uint32_t smQh = sb;
    const uint32_t smQl = sb + QTILE;
    const uint32_t smKV = sb + 2 * QTILE;

    const int tid = threadIdx.x;
    const int lane = tid & 31, wid = tid >> 5;
    const int gid = lane >> 2, tig = lane & 3;
    const int qt = (int)gridDim.x - 1 - (int)blockIdx.x;   // largest-first
    const int q0 = qt * 128;
    const int h  = blockIdx.y;
    const int b  = blockIdx.z;
    const int kvh = h >> 2;
    const int m0 = wid * 16;
    const int nkt = 2 * (qt + 1);

    #pragma unroll
    for (int j = 0; j < 8; ++j) {
        int lin = j * 256 + tid;
        int r = lin >> 4, c = lin & 15;
        size_t go = (((size_t)(b * S_LEN + q0 + r)) * NH + h) * HD + c * 8;
        cp16(smQh + r * APITCH + c * 16, g_qh + go);
        cp16(smQl + r * APITCH + c * 16, g_ql + go);
    }
    cp_kv(smKV,             g_kh, b, kvh, 0);
    cp_kv(smKV + ATILE,     g_kl, b, kvh, 0);
    cp_kv(smKV + 2 * ATILE, g_v,  b, kvh, 0);
    asm volatile("cp.async.commit_group;" ::: "memory");
    {
        uint32_t st = smKV + KVSTAGE;
        cp_kv(st,             g_kh, b, kvh, 64);
        cp_kv(st + ATILE,     g_kl, b, kvh, 64);
        cp_kv(st + 2 * ATILE, g_v,  b, kvh, 64);
        asm volatile("cp.async.commit_group;" ::: "memory");
    }

    const int qg0 = q0 + m0 + gid;
    const int qg1 = qg0 + 8;
    const int qmax = q0 + m0 + 15;
    const int csq0 = (qg0 > 0) ? g_cs[b * S_LEN + qg0 - 1] : 0;
    const int csq1 = g_cs[b * S_LEN + qg1 - 1];

    float oacc[16][4];
    #pragma unroll
    for (int d = 0; d < 16; ++d)
        #pragma unroll
        for (int q = 0; q < 4; ++q) oacc[d][q] = 0.f;
    float mrow0 = -1e30f, mrow1 = -1e30f, lrow0 = 0.f, lrow1 = 0.f;

    for (int it = 0; it < nkt; ++it) {
        const int k0 = it * 64;
        if (it + 1 < nkt) asm volatile("cp.async.wait_group 1;" ::: "memory");
        else              asm volatile("cp.async.wait_group 0;" ::: "memory");
        __syncthreads();

        if (k0 <= qmax) {
            const uint32_t st  = smKV + (it & 1) * KVSTAGE;
            const uint32_t sKh = st, sKl = st + ATILE, sV = st + 2 * ATILE;

            float sacc[8][4];
            #pragma unroll
            for (int j = 0; j < 8; ++j)
                #pragma unroll
                for (int q = 0; q < 4; ++q) sacc[j][q] = 0.f;

            const uint32_t qoff = (m0 + (lane & 15)) * APITCH + (lane >> 4) * 16;
            const uint32_t koff = (lane & 7) * APITCH + (lane >> 3) * 16;  // x4: k32
            #pragma unroll
            for (int kk2 = 0; kk2 < 4; ++kk2) {
                uint32_t qh0[4], ql0[4], qh1[4], ql1[4];
                uint32_t qa = qoff + kk2 * 64;
                ldmx4(qh0, smQh + qa);
                ldmx4(ql0, smQl + qa);
                ldmx4(qh1, smQh + qa + 32);
                ldmx4(ql1, smQl + qa + 32);
                #pragma unroll
                for (int j = 0; j < 8; ++j) {
                    uint32_t kh[4], kl[4];
                    uint32_t ka = koff + j * 8 * APITCH + kk2 * 64;
                    ldmx4(kh, sKh + ka);
                    ldmx4(kl, sKl + ka);
                    mma16816(sacc[j], qh0, kh);
                    mma16816(sacc[j], qh0, kl);
                    mma16816(sacc[j], ql0, kh);
                    mma16816(sacc[j], qh1, kh + 2);
                    mma16816(sacc[j], qh1, kl + 2);
                    mma16816(sacc[j], ql1, kh + 2);
                }
            }

            if (k0 + 73 >= q0 + m0) {
                #pragma unroll
                for (int j = 0; j < 8; ++j) {
                    int kg0 = k0 + j * 8 + tig * 2;
                    int kg1 = kg0 + 1;
                    int bi0 = kg0 + 10; if (bi0 > S_LEN - 1) bi0 = S_LEN - 1;
                    int bi1 = kg1 + 10; if (bi1 > S_LEN - 1) bi1 = S_LEN - 1;
                    int ck0 = g_cs[b * S_LEN + bi0];
                    int ck1 = g_cs[b * S_LEN + bi1];
                    if (kg0 + 10 >= qg0 && ck0 - csq0 > 0) sacc[j][0] += 2.0f;
                    if (kg1 + 10 >= qg0 && ck1 - csq0 > 0) sacc[j][1] += 2.0f;
                    if (kg0 + 10 >= qg1 && ck0 - csq1 > 0) sacc[j][2] += 2.0f;
                    if (kg1 + 10 >= qg1 && ck1 - csq1 > 0) sacc[j][3] += 2.0f;
                }
            }
            if (k0 + 63 > qg0) {
                #pragma unroll
                for (int j = 0; j < 8; ++j) {
                    int kg0 = k0 + j * 8 + tig * 2;
                    int kg1 = kg0 + 1;
                    if (kg0 > qg0) sacc[j][0] = -1e9f;
                    if (kg1 > qg0) sacc[j][1] = -1e9f;
                    if (kg0 > qg1) sacc[j][2] = -1e9f;
                    if (kg1 > qg1) sacc[j][3] = -1e9f;
                }
            }

            float mx0 = -1e30f, mx1 = -1e30f;
            #pragma unroll
            for (int j = 0; j < 8; ++j) {
                mx0 = fmaxf(mx0, fmaxf(sacc[j][0], sacc[j][1]));
                mx1 = fmaxf(mx1, fmaxf(sacc[j][2], sacc[j][3]));
            }
            mx0 = fmaxf(mx0, __shfl_xor_sync(0xffffffffu, mx0, 1));
            mx0 = fmaxf(mx0, __shfl_xor_sync(0xffffffffu, mx0, 2));
            mx1 = fmaxf(mx1, __shfl_xor_sync(0xffffffffu, mx1, 1));
            mx1 = fmaxf(mx1, __shfl_xor_sync(0xffffffffu, mx1, 2));
            float mn0 = fmaxf(mrow0, mx0), mn1 = fmaxf(mrow1, mx1);
            float a0 = __expf(mrow0 - mn0), a1 = __expf(mrow1 - mn1);
            mrow0 = mn0; mrow1 = mn1;
            float sum0 = 0.f, sum1 = 0.f;
            #pragma unroll
            for (int j = 0; j < 8; ++j) {
                sacc[j][0] = __expf(sacc[j][0] - mn0); sum0 += sacc[j][0];
                sacc[j][1] = __expf(sacc[j][1] - mn0); sum0 += sacc[j][1];
                sacc[j][2] = __expf(sacc[j][2] - mn1); sum1 += sacc[j][2];
                sacc[j][3] = __expf(sacc[j][3] - mn1); sum1 += sacc[j][3];
            }
            sum0 += __shfl_xor_sync(0xffffffffu, sum0, 1);
            sum0 += __shfl_xor_sync(0xffffffffu, sum0, 2);
            sum1 += __shfl_xor_sync(0xffffffffu, sum1, 1);
            sum1 += __shfl_xor_sync(0xffffffffu, sum1, 2);
            lrow0 = lrow0 * a0 + sum0;
            lrow1 = lrow1 * a1 + sum1;
            #pragma unroll
            for (int d = 0; d < 16; ++d) {
                oacc[d][0] *= a0; oacc[d][1] *= a0;
                oacc[d][2] *= a1; oacc[d][3] *= a1;
            }

            uint32_t ph[4][4];
            #pragma unroll
            for (int t = 0; t < 4; ++t) {
                int j0 = 2 * t, j1 = 2 * t + 1;
                ph[t][0] = pack_h(sacc[j0][0], sacc[j0][1]);
                ph[t][1] = pack_h(sacc[j0][2], sacc[j0][3]);
                ph[t][2] = pack_h(sacc[j1][0], sacc[j1][1]);
                ph[t][3] = pack_h(sacc[j1][2], sacc[j1][3]);
            }

            const uint32_t voff = (lane & 15) * APITCH + (lane >> 4) * 16;
            #pragma unroll
            for (int t = 0; t < 4; ++t) {
                #pragma unroll
                for (int dn2 = 0; dn2 < 8; ++dn2) {
                    uint32_t vh[4];
                    ldmx4t(vh, sV + voff + t * 16 * APITCH + dn2 * 32);
                    mma16816(oacc[2 * dn2],     ph[t], vh);
                    mma16816(oacc[2 * dn2 + 1], ph[t], vh + 2);
                }
            }
        }
        __syncthreads();

        if (it + 2 < nkt) {
            uint32_t pst = smKV + (it & 1) * KVSTAGE;
            int row0 = (it + 2) * 64;
            cp_kv(pst,             g_kh, b, kvh, row0);
            cp_kv(pst + ATILE,     g_kl, b, kvh, row0);
            cp_kv(pst + 2 * ATILE, g_v,  b, kvh, row0);
            asm volatile("cp.async.commit_group;" ::: "memory");
        }
    }

    float il0 = 1.0f / lrow0, il1 = 1.0f / lrow1;
    size_t b0 = (((size_t)(b * S_LEN + qg0)) * NH + h) * HD + tig * 2;
    size_t b1 = (((size_t)(b * S_LEN + qg1)) * NH + h) * HD + tig * 2;
    #pragma unroll
    for (int d = 0; d < 16; ++d) {
        *(uint32_t*)(g_ao + b0 + d * 8) = pack_h(oacc[d][0] * il0, oacc[d][1] * il0);
        *(uint32_t*)(g_ao + b1 + d * 8) = pack_h(oacc[d][2] * il1, oacc[d][3] * il1);
    }
}

// ---------------- launch ----------------------------------------------------
extern "C" void kernel_launch(void* const* d_in, const int* in_sizes, int n_in,
                              void* d_out, int out_size) {
    const float* x      = (const float*)d_in[0];
    const float* freqs  = (const float*)d_in[2];
    const int*   labels = (const int*)d_in[4];
    const float* wq     = (const float*)d_in[5];
    const float* wk     = (const float*)d_in[6];
    const float* wv     = (const float*)d_in[7];
    const float* wo     = (const float*)d_in[8];
    const float* ln1w   = (const float*)d_in[9];
    const float* ln1b   = (const float*)d_in[10];
    const float* ln2w   = (const float*)d_in[11];
    const float* ln2b   = (const float*)d_in[12];
    float* out = (float*)d_out;

    __half *xnh, *xnl, *ao;
    cudaGetSymbolAddress((void**)&xnh, g_xn_h);
    cudaGetSymbolAddress((void**)&xnl, g_xn_l);
    cudaGetSymbolAddress((void**)&ao,  g_ao);

    split_all<<<TOT_F4 / 1024, 256>>>(wq, wk, wv, wo);
    ln_kernel<<<ROWS, 256>>>(x, ln1w, ln1b, xnh, xnl);
    cumsum_kernel<<<2, 1024>>>(labels);

    size_t gemm_smem = 2 * STAGE_B;    // 65536 (3-term layout; V branch uses subset)
    size_t o_smem    = 2 * STAGE1_B;   // 32768 (1-term layout; max L1 carveout)
    cudaFuncSetAttribute(qkv_gemm, cudaFuncAttributeMaxDynamicSharedMemorySize, (int)gemm_smem);
    cudaFuncSetAttribute(o_gemm, cudaFuncAttributeMaxDynamicSharedMemorySize, (int)o_smem);

    const float qscale = 0.08838834764831845f;   // 1/sqrt(128)
    qkv_gemm<<<dim3(24, ROWS / 128), 256, gemm_smem>>>(freqs, qscale);

    size_t attn_smem = 2 * QTILE + 2 * KVSTAGE;   // 174080
    cudaFuncSetAttribute(attn_kernel, cudaFuncAttributeMaxDynamicSharedMemorySize,
                         (int)attn_smem);
    attn_kernel<<<dim3(S_LEN / 128, NH, 2), 256, attn_smem>>>();

    ln_kernel_h<<<ROWS, 256>>>(ao, ln2w, ln2b, xnh, xnl);
    o_gemm<<<dim3(DIMN / 128, ROWS / 128), 256, o_smem>>>(out);
}